// round 4
// baseline (speedup 1.0000x reference)
#include <cuda_runtime.h>
#include <cstdint>

#define EB    1024
#define HN    16
#define DH    64
#define BB    2
#define SS    2048
#define MT    (BB*SS)       // 4096
#define E3    (3*EB)        // 3072

// Scratch (device globals — allocation is forbidden)
__device__ float g_qkv[(size_t)MT * E3];      // [token][3E]
__device__ float g_attn[(size_t)MT * EB];     // [token][E]
__device__ float g_rowsum[BB * HN * SS];

// =====================================================================
// SGEMM: C[M,N] = A[M,K] @ B[N,K]^T + bias[N]
// 128x128 tile, BK=8, 256 threads, thread (tx,ty) computes
// rows row0+ty*8+i (i<8), cols col0+tx*8+j (j<8). Plain scalar FMA.
// =====================================================================
__global__ __launch_bounds__(256) void sgemm_bias_nt(
    const float* __restrict__ A, const float* __restrict__ B,
    const float* __restrict__ bias, float* __restrict__ C,
    int M, int N, int K)
{
    __shared__ float As[8][132];
    __shared__ float Bs[8][132];
    const int tid = threadIdx.x;
    const int tx = tid & 15, ty = tid >> 4;
    const int row0 = blockIdx.y * 128, col0 = blockIdx.x * 128;
    const int lm = tid >> 1;            // 0..127
    const int lk = (tid & 1) * 4;       // 0 or 4

    float acc[8][8];
    #pragma unroll
    for (int i = 0; i < 8; i++)
        #pragma unroll
        for (int j = 0; j < 8; j++) acc[i][j] = 0.0f;

    for (int k0 = 0; k0 < K; k0 += 8) {
        float4 va = *(const float4*)&A[(size_t)(row0 + lm) * K + k0 + lk];
        As[lk + 0][lm] = va.x; As[lk + 1][lm] = va.y;
        As[lk + 2][lm] = va.z; As[lk + 3][lm] = va.w;
        float4 vb = *(const float4*)&B[(size_t)(col0 + lm) * K + k0 + lk];
        Bs[lk + 0][lm] = vb.x; Bs[lk + 1][lm] = vb.y;
        Bs[lk + 2][lm] = vb.z; Bs[lk + 3][lm] = vb.w;
        __syncthreads();
        #pragma unroll
        for (int kk = 0; kk < 8; kk++) {
            float a[8], b[8];
            #pragma unroll
            for (int i = 0; i < 8; i++) a[i] = As[kk][ty * 8 + i];
            #pragma unroll
            for (int j = 0; j < 8; j++) b[j] = Bs[kk][tx * 8 + j];
            #pragma unroll
            for (int i = 0; i < 8; i++)
                #pragma unroll
                for (int j = 0; j < 8; j++)
                    acc[i][j] = fmaf(a[i], b[j], acc[i][j]);
        }
        __syncthreads();
    }

    #pragma unroll
    for (int i = 0; i < 8; i++) {
        int r = row0 + ty * 8 + i;
        #pragma unroll
        for (int j = 0; j < 8; j++) {
            int c = col0 + tx * 8 + j;
            C[(size_t)r * N + c] = acc[i][j] + bias[c];
        }
    }
}

// =====================================================================
// Scores+exp: attw[bh,q,k] = exp( (Q·K) / 8 )   (unnormalized)
// Q/K are [S,64] strided (stride E3) views into g_qkv.
// Grid: (S/128, S/128, B*H)
// =====================================================================
__global__ __launch_bounds__(256) void scores_exp_kernel(float* __restrict__ attw)
{
    __shared__ float As[8][132];
    __shared__ float Bs[8][132];
    const int tid = threadIdx.x;
    const int tx = tid & 15, ty = tid >> 4;
    const int bh = blockIdx.z;
    const int b = bh >> 4, h = bh & 15;
    const float* Qp = g_qkv + (size_t)b * SS * E3 + h * DH;
    const float* Kp = Qp + EB;
    const int row0 = blockIdx.y * 128, col0 = blockIdx.x * 128;
    const int lm = tid >> 1;
    const int lk = (tid & 1) * 4;

    float acc[8][8];
    #pragma unroll
    for (int i = 0; i < 8; i++)
        #pragma unroll
        for (int j = 0; j < 8; j++) acc[i][j] = 0.0f;

    #pragma unroll
    for (int k0 = 0; k0 < DH; k0 += 8) {
        float4 va = *(const float4*)&Qp[(size_t)(row0 + lm) * E3 + k0 + lk];
        As[lk + 0][lm] = va.x; As[lk + 1][lm] = va.y;
        As[lk + 2][lm] = va.z; As[lk + 3][lm] = va.w;
        float4 vb = *(const float4*)&Kp[(size_t)(col0 + lm) * E3 + k0 + lk];
        Bs[lk + 0][lm] = vb.x; Bs[lk + 1][lm] = vb.y;
        Bs[lk + 2][lm] = vb.z; Bs[lk + 3][lm] = vb.w;
        __syncthreads();
        #pragma unroll
        for (int kk = 0; kk < 8; kk++) {
            float a[8], bb[8];
            #pragma unroll
            for (int i = 0; i < 8; i++) a[i] = As[kk][ty * 8 + i];
            #pragma unroll
            for (int j = 0; j < 8; j++) bb[j] = Bs[kk][tx * 8 + j];
            #pragma unroll
            for (int i = 0; i < 8; i++)
                #pragma unroll
                for (int j = 0; j < 8; j++)
                    acc[i][j] = fmaf(a[i], bb[j], acc[i][j]);
        }
        __syncthreads();
    }

    float* Cb = attw + (size_t)bh * SS * SS;
    #pragma unroll
    for (int i = 0; i < 8; i++) {
        int r = row0 + ty * 8 + i;
        #pragma unroll
        for (int j = 0; j < 8; j++) {
            int c = col0 + tx * 8 + j;
            Cb[(size_t)r * SS + c] = __expf(acc[i][j] * 0.125f);
        }
    }
}

// =====================================================================
// Rowsum: g_rowsum[row] = sum_k attw[row][k]. One block per row.
// =====================================================================
__global__ __launch_bounds__(256) void rowsum_kernel(const float* __restrict__ attw)
{
    __shared__ float sm[256];
    const int tid = threadIdx.x;
    const size_t row = blockIdx.x;
    const float* p = attw + row * SS;
    float s = 0.0f;
    for (int i = tid; i < SS; i += 256) s += p[i];
    sm[tid] = s;
    __syncthreads();
    for (int o = 128; o > 0; o >>= 1) {
        if (tid < o) sm[tid] += sm[tid + o];
        __syncthreads();
    }
    if (tid == 0) g_rowsum[row] = sm[0];
}

// =====================================================================
// Normalize: attw /= rowsum
// =====================================================================
__global__ __launch_bounds__(256) void norm_kernel(float* __restrict__ attw)
{
    size_t i4 = (size_t)blockIdx.x * 256 + threadIdx.x;   // float4 index
    size_t row = i4 >> 9;                                  // 512 float4 per row
    float inv = 1.0f / g_rowsum[row];
    float4* p = (float4*)attw;
    float4 v = p[i4];
    v.x *= inv; v.y *= inv; v.z *= inv; v.w *= inv;
    p[i4] = v;
}

// =====================================================================
// PV: g_attn[b, s, h*64+d] = sum_k P[bh,s,k] * V[bh,k,d]
// 128x64 tile, BK=8, 256 threads; thread (tx 0..7, ty 0..31):
// rows row0+ty*4+i (i<4), cols tx*8+j (j<8).
// Grid: (S/128, 1, B*H)
// =====================================================================
__global__ __launch_bounds__(256) void pv_kernel(const float* __restrict__ attw)
{
    __shared__ float As[8][132];
    __shared__ float Bs[8][68];
    const int tid = threadIdx.x;
    const int tx = tid & 7, ty = tid >> 3;
    const int bh = blockIdx.z;
    const int b = bh >> 4, h = bh & 15;
    const float* P = attw + (size_t)bh * SS * SS;
    const float* V = g_qkv + (size_t)b * SS * E3 + 2 * EB + h * DH;
    const int row0 = blockIdx.x * 128;
    const int lm = tid >> 1;
    const int lk = (tid & 1) * 4;

    float acc[4][8];
    #pragma unroll
    for (int i = 0; i < 4; i++)
        #pragma unroll
        for (int j = 0; j < 8; j++) acc[i][j] = 0.0f;

    for (int k0 = 0; k0 < SS; k0 += 8) {
        float4 va = *(const float4*)&P[(size_t)(row0 + lm) * SS + k0 + lk];
        As[lk + 0][lm] = va.x; As[lk + 1][lm] = va.y;
        As[lk + 2][lm] = va.z; As[lk + 3][lm] = va.w;
        #pragma unroll
        for (int t = 0; t < 2; t++) {
            int e = t * 256 + tid;           // 0..511
            int kc = e >> 6, n = e & 63;
            Bs[kc][n] = V[(size_t)(k0 + kc) * E3 + n];
        }
        __syncthreads();
        #pragma unroll
        for (int kk = 0; kk < 8; kk++) {
            float a[4], bb[8];
            #pragma unroll
            for (int i = 0; i < 4; i++) a[i] = As[kk][ty * 4 + i];
            #pragma unroll
            for (int j = 0; j < 8; j++) bb[j] = Bs[kk][tx * 8 + j];
            #pragma unroll
            for (int i = 0; i < 4; i++)
                #pragma unroll
                for (int j = 0; j < 8; j++)
                    acc[i][j] = fmaf(a[i], bb[j], acc[i][j]);
        }
        __syncthreads();
    }

    #pragma unroll
    for (int i = 0; i < 4; i++) {
        int s = row0 + ty * 4 + i;
        #pragma unroll
        for (int j = 0; j < 8; j++) {
            g_attn[(size_t)(b * SS + s) * EB + h * DH + tx * 8 + j] = acc[i][j];
        }
    }
}

// =====================================================================
extern "C" void kernel_launch(void* const* d_in, const int* in_sizes, int n_in,
                              void* d_out, int out_size)
{
    (void)in_sizes; (void)n_in; (void)out_size;
    const float* x     = (const float*)d_in[0];   // [2,2048,1024]
    const float* qkv_w = (const float*)d_in[1];   // [3072,1024]
    const float* qkv_b = (const float*)d_in[2];   // [3072]
    const float* out_w = (const float*)d_in[3];   // [1024,1024]
    const float* out_b = (const float*)d_in[4];   // [1024]

    float* out  = (float*)d_out;                  // output: [2,2048,1024]
    float* attw = out + (size_t)MT * EB;          // attn_weights: [2,16,2048,2048]

    // CRITICAL FIX: resolve the true DEVICE addresses of __device__ globals.
    // Referencing g_qkv/g_attn by name in host code yields the host shadow
    // symbol; on GB300 (ATS) kernels silently dereference host memory.
    float* d_qkv  = nullptr;
    float* d_attn = nullptr;
    cudaGetSymbolAddress((void**)&d_qkv,  g_qkv);
    cudaGetSymbolAddress((void**)&d_attn, g_attn);

    // 1. QKV projection: g_qkv = x @ qkv_w^T + qkv_b
    {
        dim3 grid(E3 / 128, MT / 128);
        sgemm_bias_nt<<<grid, 256>>>(x, qkv_w, qkv_b, d_qkv, MT, E3, EB);
    }
    // 2. scores + exp (unnormalized)
    {
        dim3 grid(SS / 128, SS / 128, BB * HN);
        scores_exp_kernel<<<grid, 256>>>(attw);
    }
    // 3. row sums
    rowsum_kernel<<<BB * HN * SS, 256>>>(attw);
    // 4. normalize
    {
        size_t n4 = (size_t)BB * HN * SS * SS / 4;
        norm_kernel<<<(unsigned)(n4 / 256), 256>>>(attw);
    }
    // 5. P @ V
    {
        dim3 grid(SS / 128, 1, BB * HN);
        pv_kernel<<<grid, 256>>>(attw);
    }
    // 6. out projection
    {
        dim3 grid(EB / 128, MT / 128);
        sgemm_bias_nt<<<grid, 256>>>(d_attn, out_w, out_b, out, MT, EB, EB);
    }
}

// round 5
// speedup vs baseline: 1.3071x; 1.3071x over previous
#include <cuda_runtime.h>
#include <cstdint>

#define EB    1024
#define HN    16
#define DH    64
#define BB    2
#define SS    2048
#define MT    (BB*SS)       // 4096
#define E3    (3*EB)        // 3072

typedef unsigned long long u64;

// Scratch (device globals — allocation is forbidden)
__device__ float g_qkv[(size_t)MT * E3];      // [token][3E]
__device__ float g_attn[(size_t)MT * EB];     // [token][E]
__device__ float g_rowsum[BB * HN * SS];      // [bh*S + row]
__device__ float g_part[(size_t)BB * HN * SS * 16];   // per-colblock partials

// ---------------- packed f32x2 helpers (B300 FFMA2) ----------------
__device__ __forceinline__ u64 pack2(float x, float y) {
    u64 r;
    asm("mov.b64 %0, {%1, %2};" : "=l"(r) : "r"(__float_as_uint(x)), "r"(__float_as_uint(y)));
    return r;
}
__device__ __forceinline__ void unpack2(u64 v, float& x, float& y) {
    unsigned lo, hi;
    asm("mov.b64 {%0, %1}, %2;" : "=r"(lo), "=r"(hi) : "l"(v));
    x = __uint_as_float(lo); y = __uint_as_float(hi);
}
__device__ __forceinline__ u64 fma2(u64 a, u64 b, u64 c) {
    u64 d;
    asm("fma.rn.f32x2 %0, %1, %2, %3;" : "=l"(d) : "l"(a), "l"(b), "l"(c));
    return d;
}

// =====================================================================
// SGEMM: C[M,N] = A[M,K] @ B[N,K]^T + bias[N]
// 128x128 tile, BK=8, 256 threads; thread (tx 0..15, ty 0..15) computes
// rows row0+ty*8+i (i<8), cols col0+tx*8+2*jp(+1) (jp<4). FFMA2 accum.
// =====================================================================
__global__ __launch_bounds__(256) void sgemm_bias_nt(
    const float* __restrict__ A, const float* __restrict__ B,
    const float* __restrict__ bias, float* __restrict__ C,
    int M, int N, int K)
{
    __shared__ float As[8][132];
    __shared__ float Bs[8][132];
    const int tid = threadIdx.x;
    const int tx = tid & 15, ty = tid >> 4;
    const int row0 = blockIdx.y * 128, col0 = blockIdx.x * 128;
    const int lm = tid >> 1;            // 0..127
    const int lk = (tid & 1) * 4;       // 0 or 4

    u64 acc[8][4];
    #pragma unroll
    for (int i = 0; i < 8; i++)
        #pragma unroll
        for (int j = 0; j < 4; j++) acc[i][j] = 0ull;

    for (int k0 = 0; k0 < K; k0 += 8) {
        float4 va = *(const float4*)&A[(size_t)(row0 + lm) * K + k0 + lk];
        As[lk + 0][lm] = va.x; As[lk + 1][lm] = va.y;
        As[lk + 2][lm] = va.z; As[lk + 3][lm] = va.w;
        float4 vb = *(const float4*)&B[(size_t)(col0 + lm) * K + k0 + lk];
        Bs[lk + 0][lm] = vb.x; Bs[lk + 1][lm] = vb.y;
        Bs[lk + 2][lm] = vb.z; Bs[lk + 3][lm] = vb.w;
        __syncthreads();
        #pragma unroll
        for (int kk = 0; kk < 8; kk++) {
            float4 a0 = *(const float4*)&As[kk][ty * 8];
            float4 a1 = *(const float4*)&As[kk][ty * 8 + 4];
            float4 b0 = *(const float4*)&Bs[kk][tx * 8];
            float4 b1 = *(const float4*)&Bs[kk][tx * 8 + 4];
            float a[8] = {a0.x, a0.y, a0.z, a0.w, a1.x, a1.y, a1.z, a1.w};
            u64 bb[4] = {pack2(b0.x, b0.y), pack2(b0.z, b0.w),
                         pack2(b1.x, b1.y), pack2(b1.z, b1.w)};
            #pragma unroll
            for (int i = 0; i < 8; i++) {
                u64 ad = pack2(a[i], a[i]);
                #pragma unroll
                for (int j = 0; j < 4; j++) acc[i][j] = fma2(ad, bb[j], acc[i][j]);
            }
        }
        __syncthreads();
    }

    const int c0 = col0 + tx * 8;
    float bx0 = bias[c0 + 0], bx1 = bias[c0 + 1], bx2 = bias[c0 + 2], bx3 = bias[c0 + 3];
    float bx4 = bias[c0 + 4], bx5 = bias[c0 + 5], bx6 = bias[c0 + 6], bx7 = bias[c0 + 7];
    #pragma unroll
    for (int i = 0; i < 8; i++) {
        int r = row0 + ty * 8 + i;
        float v0, v1, v2, v3, v4, v5, v6, v7;
        unpack2(acc[i][0], v0, v1); unpack2(acc[i][1], v2, v3);
        unpack2(acc[i][2], v4, v5); unpack2(acc[i][3], v6, v7);
        *(float4*)&C[(size_t)r * N + c0]     = make_float4(v0 + bx0, v1 + bx1, v2 + bx2, v3 + bx3);
        *(float4*)&C[(size_t)r * N + c0 + 4] = make_float4(v4 + bx4, v5 + bx5, v6 + bx6, v7 + bx7);
    }
}

// =====================================================================
// Scores+exp: attw[bh,q,k] = exp((Q·K)/8) (unnormalized) + row partials
// Grid: (S/128, S/128, B*H). Partial sums: g_part[(bh*S+row)*16 + colblk]
// =====================================================================
__global__ __launch_bounds__(256) void scores_exp_kernel(float* __restrict__ attw)
{
    __shared__ float As[8][132];
    __shared__ float Bs[8][132];
    const int tid = threadIdx.x;
    const int tx = tid & 15, ty = tid >> 4;
    const int bh = blockIdx.z;
    const int b = bh >> 4, h = bh & 15;
    const float* Qp = g_qkv + (size_t)b * SS * E3 + h * DH;
    const float* Kp = Qp + EB;
    const int row0 = blockIdx.y * 128, col0 = blockIdx.x * 128;
    const int lm = tid >> 1;
    const int lk = (tid & 1) * 4;

    u64 acc[8][4];
    #pragma unroll
    for (int i = 0; i < 8; i++)
        #pragma unroll
        for (int j = 0; j < 4; j++) acc[i][j] = 0ull;

    #pragma unroll
    for (int k0 = 0; k0 < DH; k0 += 8) {
        float4 va = *(const float4*)&Qp[(size_t)(row0 + lm) * E3 + k0 + lk];
        As[lk + 0][lm] = va.x; As[lk + 1][lm] = va.y;
        As[lk + 2][lm] = va.z; As[lk + 3][lm] = va.w;
        float4 vb = *(const float4*)&Kp[(size_t)(col0 + lm) * E3 + k0 + lk];
        Bs[lk + 0][lm] = vb.x; Bs[lk + 1][lm] = vb.y;
        Bs[lk + 2][lm] = vb.z; Bs[lk + 3][lm] = vb.w;
        __syncthreads();
        #pragma unroll
        for (int kk = 0; kk < 8; kk++) {
            float4 a0 = *(const float4*)&As[kk][ty * 8];
            float4 a1 = *(const float4*)&As[kk][ty * 8 + 4];
            float4 b0 = *(const float4*)&Bs[kk][tx * 8];
            float4 b1 = *(const float4*)&Bs[kk][tx * 8 + 4];
            float a[8] = {a0.x, a0.y, a0.z, a0.w, a1.x, a1.y, a1.z, a1.w};
            u64 bb[4] = {pack2(b0.x, b0.y), pack2(b0.z, b0.w),
                         pack2(b1.x, b1.y), pack2(b1.z, b1.w)};
            #pragma unroll
            for (int i = 0; i < 8; i++) {
                u64 ad = pack2(a[i], a[i]);
                #pragma unroll
                for (int j = 0; j < 4; j++) acc[i][j] = fma2(ad, bb[j], acc[i][j]);
            }
        }
        __syncthreads();
    }

    float* Cb = attw + (size_t)bh * SS * SS;
    const int c0 = col0 + tx * 8;
    #pragma unroll
    for (int i = 0; i < 8; i++) {
        int r = row0 + ty * 8 + i;
        float v[8];
        unpack2(acc[i][0], v[0], v[1]); unpack2(acc[i][1], v[2], v[3]);
        unpack2(acc[i][2], v[4], v[5]); unpack2(acc[i][3], v[6], v[7]);
        float rp = 0.0f;
        #pragma unroll
        for (int j = 0; j < 8; j++) { v[j] = __expf(v[j] * 0.125f); rp += v[j]; }
        *(float4*)&Cb[(size_t)r * SS + c0]     = make_float4(v[0], v[1], v[2], v[3]);
        *(float4*)&Cb[(size_t)r * SS + c0 + 4] = make_float4(v[4], v[5], v[6], v[7]);
        // deterministic half-warp reduction over tx (lanes 0-15 / 16-31)
        #pragma unroll
        for (int m = 1; m < 16; m <<= 1)
            rp += __shfl_xor_sync(0xffffffffu, rp, m);
        if (tx == 0)
            g_part[((size_t)bh * SS + r) * 16 + blockIdx.x] = rp;
    }
}

// =====================================================================
// Fold 16 col-block partials per row -> g_rowsum. One thread per row.
// =====================================================================
__global__ __launch_bounds__(256) void rowsum_fold_kernel()
{
    int row = blockIdx.x * 256 + threadIdx.x;      // 0 .. BB*HN*SS-1
    const float* p = &g_part[(size_t)row * 16];
    float s = 0.0f;
    #pragma unroll
    for (int i = 0; i < 16; i++) s += p[i];
    g_rowsum[row] = s;
}

// =====================================================================
// Normalize: attw /= rowsum
// =====================================================================
__global__ __launch_bounds__(256) void norm_kernel(float* __restrict__ attw)
{
    size_t i4 = (size_t)blockIdx.x * 256 + threadIdx.x;   // float4 index
    size_t row = i4 >> 9;                                  // 512 float4/row
    float inv = 1.0f / g_rowsum[row];
    float4* p = (float4*)attw;
    float4 v = p[i4];
    v.x *= inv; v.y *= inv; v.z *= inv; v.w *= inv;
    p[i4] = v;
}

// =====================================================================
// PV: g_attn[b,s,h*64+d] = sum_k P[bh,s,k] * V[bh,k,d]
// 128x64 tile, BK=8, 256 threads; thread (tx 0..7, ty 0..31):
// rows row0+ty*4+i (i<4), cols tx*8+2*jp(+1). FFMA2 accum.
// Grid: (S/128, 1, B*H)
// =====================================================================
__global__ __launch_bounds__(256) void pv_kernel(const float* __restrict__ attw)
{
    __shared__ float As[8][132];
    __shared__ float Bs[8][68];
    const int tid = threadIdx.x;
    const int tx = tid & 7, ty = tid >> 3;
    const int bh = blockIdx.z;
    const int b = bh >> 4, h = bh & 15;
    const float* P = attw + (size_t)bh * SS * SS;
    const float* V = g_qkv + (size_t)b * SS * E3 + 2 * EB + h * DH;
    const int row0 = blockIdx.x * 128;
    const int lm = tid >> 1;
    const int lk = (tid & 1) * 4;

    u64 acc[4][4];
    #pragma unroll
    for (int i = 0; i < 4; i++)
        #pragma unroll
        for (int j = 0; j < 4; j++) acc[i][j] = 0ull;

    for (int k0 = 0; k0 < SS; k0 += 8) {
        float4 va = *(const float4*)&P[(size_t)(row0 + lm) * SS + k0 + lk];
        As[lk + 0][lm] = va.x; As[lk + 1][lm] = va.y;
        As[lk + 2][lm] = va.z; As[lk + 3][lm] = va.w;
        #pragma unroll
        for (int t = 0; t < 2; t++) {
            int e = t * 256 + tid;           // 0..511
            int kc = e >> 6, n = e & 63;
            Bs[kc][n] = V[(size_t)(k0 + kc) * E3 + n];
        }
        __syncthreads();
        #pragma unroll
        for (int kk = 0; kk < 8; kk++) {
            float4 av = *(const float4*)&As[kk][ty * 4];
            float4 b0 = *(const float4*)&Bs[kk][tx * 8];
            float4 b1 = *(const float4*)&Bs[kk][tx * 8 + 4];
            float a[4] = {av.x, av.y, av.z, av.w};
            u64 bb[4] = {pack2(b0.x, b0.y), pack2(b0.z, b0.w),
                         pack2(b1.x, b1.y), pack2(b1.z, b1.w)};
            #pragma unroll
            for (int i = 0; i < 4; i++) {
                u64 ad = pack2(a[i], a[i]);
                #pragma unroll
                for (int j = 0; j < 4; j++) acc[i][j] = fma2(ad, bb[j], acc[i][j]);
            }
        }
        __syncthreads();
    }

    #pragma unroll
    for (int i = 0; i < 4; i++) {
        int s = row0 + ty * 4 + i;
        float v0, v1, v2, v3, v4, v5, v6, v7;
        unpack2(acc[i][0], v0, v1); unpack2(acc[i][1], v2, v3);
        unpack2(acc[i][2], v4, v5); unpack2(acc[i][3], v6, v7);
        float* o = &g_attn[(size_t)(b * SS + s) * EB + h * DH + tx * 8];
        *(float4*)&o[0] = make_float4(v0, v1, v2, v3);
        *(float4*)&o[4] = make_float4(v4, v5, v6, v7);
    }
}

// =====================================================================
extern "C" void kernel_launch(void* const* d_in, const int* in_sizes, int n_in,
                              void* d_out, int out_size)
{
    (void)in_sizes; (void)n_in; (void)out_size;
    const float* x     = (const float*)d_in[0];   // [2,2048,1024]
    const float* qkv_w = (const float*)d_in[1];   // [3072,1024]
    const float* qkv_b = (const float*)d_in[2];   // [3072]
    const float* out_w = (const float*)d_in[3];   // [1024,1024]
    const float* out_b = (const float*)d_in[4];   // [1024]

    float* out  = (float*)d_out;                  // output: [2,2048,1024]
    float* attw = out + (size_t)MT * EB;          // attn_weights: [2,16,2048,2048]

    // Resolve true DEVICE addresses of __device__ globals (host shadow
    // symbols are silently dereferenced via ATS on GB300 otherwise).
    float* d_qkv  = nullptr;
    float* d_attn = nullptr;
    cudaGetSymbolAddress((void**)&d_qkv,  g_qkv);
    cudaGetSymbolAddress((void**)&d_attn, g_attn);

    // 1. QKV projection
    {
        dim3 grid(E3 / 128, MT / 128);
        sgemm_bias_nt<<<grid, 256>>>(x, qkv_w, qkv_b, d_qkv, MT, E3, EB);
    }
    // 2. scores + exp + row partials
    {
        dim3 grid(SS / 128, SS / 128, BB * HN);
        scores_exp_kernel<<<grid, 256>>>(attw);
    }
    // 3. fold partials
    rowsum_fold_kernel<<<BB * HN * SS / 256, 256>>>();
    // 4. normalize
    {
        size_t n4 = (size_t)BB * HN * SS * SS / 4;
        norm_kernel<<<(unsigned)(n4 / 256), 256>>>(attw);
    }
    // 5. P @ V
    {
        dim3 grid(SS / 128, 1, BB * HN);
        pv_kernel<<<grid, 256>>>(attw);
    }
    // 6. out projection
    {
        dim3 grid(EB / 128, MT / 128);
        sgemm_bias_nt<<<grid, 256>>>(d_attn, out_w, out_b, out, MT, EB, EB);
    }
}

// round 6
// speedup vs baseline: 1.3479x; 1.0312x over previous
#include <cuda_runtime.h>
#include <cstdint>

#define EB    1024
#define HN    16
#define DH    64
#define BB    2
#define SS    2048
#define MT    (BB*SS)       // 4096
#define E3    (3*EB)        // 3072

typedef unsigned long long u64;

// Scratch (device globals — allocation is forbidden)
__device__ float g_qkv[(size_t)MT * E3];      // [token][3E]
__device__ float g_attn[(size_t)MT * EB];     // [token][E]
__device__ float g_rowsum[BB * HN * SS];      // [bh*S + row]
__device__ float g_part[(size_t)BB * HN * SS * 16];   // per-colblock partials

// ---------------- packed f32x2 helpers (B300 FFMA2) ----------------
__device__ __forceinline__ u64 pack2(float x, float y) {
    u64 r;
    asm("mov.b64 %0, {%1, %2};" : "=l"(r) : "r"(__float_as_uint(x)), "r"(__float_as_uint(y)));
    return r;
}
__device__ __forceinline__ void unpack2(u64 v, float& x, float& y) {
    unsigned lo, hi;
    asm("mov.b64 {%0, %1}, %2;" : "=r"(lo), "=r"(hi) : "l"(v));
    x = __uint_as_float(lo); y = __uint_as_float(hi);
}
__device__ __forceinline__ u64 fma2(u64 a, u64 b, u64 c) {
    u64 d;
    asm("fma.rn.f32x2 %0, %1, %2, %3;" : "=l"(d) : "l"(a), "l"(b), "l"(c));
    return d;
}

// =====================================================================
// SGEMM: C[M,N] = A[M,K] @ B[N,K]^T + bias[N]
// 128x128 tile, BK=16, double-buffered smem, 256 threads.
// Thread (tx,ty): rows row0+ty*8+i, cols col0+tx*8+j. FFMA2 accum.
// =====================================================================
__global__ __launch_bounds__(256) void sgemm_bias_nt(
    const float* __restrict__ A, const float* __restrict__ B,
    const float* __restrict__ bias, float* __restrict__ C,
    int M, int N, int K)
{
    __shared__ float As[2][16][132];
    __shared__ float Bs[2][16][132];
    const int tid = threadIdx.x;
    const int tx = tid & 15, ty = tid >> 4;
    const int row0 = blockIdx.y * 128, col0 = blockIdx.x * 128;
    const int lm = tid >> 1;            // 0..127
    const int lk = (tid & 1) * 8;       // 0 or 8

    const float* Ap = A + (size_t)(row0 + lm) * K + lk;
    const float* Bp = B + (size_t)(col0 + lm) * K + lk;

    u64 acc[8][4];
    #pragma unroll
    for (int i = 0; i < 8; i++)
        #pragma unroll
        for (int j = 0; j < 4; j++) acc[i][j] = 0ull;

    // preload tile 0
    {
        float4 a0 = *(const float4*)(Ap);
        float4 a1 = *(const float4*)(Ap + 4);
        float4 b0 = *(const float4*)(Bp);
        float4 b1 = *(const float4*)(Bp + 4);
        As[0][lk + 0][lm] = a0.x; As[0][lk + 1][lm] = a0.y;
        As[0][lk + 2][lm] = a0.z; As[0][lk + 3][lm] = a0.w;
        As[0][lk + 4][lm] = a1.x; As[0][lk + 5][lm] = a1.y;
        As[0][lk + 6][lm] = a1.z; As[0][lk + 7][lm] = a1.w;
        Bs[0][lk + 0][lm] = b0.x; Bs[0][lk + 1][lm] = b0.y;
        Bs[0][lk + 2][lm] = b0.z; Bs[0][lk + 3][lm] = b0.w;
        Bs[0][lk + 4][lm] = b1.x; Bs[0][lk + 5][lm] = b1.y;
        Bs[0][lk + 6][lm] = b1.z; Bs[0][lk + 7][lm] = b1.w;
    }
    __syncthreads();

    int buf = 0;
    for (int k0 = 0; k0 < K; k0 += 16) {
        float4 pa0, pa1, pb0, pb1;
        const bool more = (k0 + 16 < K);
        if (more) {
            pa0 = *(const float4*)(Ap + k0 + 16);
            pa1 = *(const float4*)(Ap + k0 + 20);
            pb0 = *(const float4*)(Bp + k0 + 16);
            pb1 = *(const float4*)(Bp + k0 + 20);
        }
        #pragma unroll
        for (int kk = 0; kk < 16; kk++) {
            float4 fa0 = *(const float4*)&As[buf][kk][ty * 8];
            float4 fa1 = *(const float4*)&As[buf][kk][ty * 8 + 4];
            float4 fb0 = *(const float4*)&Bs[buf][kk][tx * 8];
            float4 fb1 = *(const float4*)&Bs[buf][kk][tx * 8 + 4];
            float a[8] = {fa0.x, fa0.y, fa0.z, fa0.w, fa1.x, fa1.y, fa1.z, fa1.w};
            u64 bb[4] = {pack2(fb0.x, fb0.y), pack2(fb0.z, fb0.w),
                         pack2(fb1.x, fb1.y), pack2(fb1.z, fb1.w)};
            #pragma unroll
            for (int i = 0; i < 8; i++) {
                u64 ad = pack2(a[i], a[i]);
                #pragma unroll
                for (int j = 0; j < 4; j++) acc[i][j] = fma2(ad, bb[j], acc[i][j]);
            }
        }
        if (more) {
            int nb = buf ^ 1;
            As[nb][lk + 0][lm] = pa0.x; As[nb][lk + 1][lm] = pa0.y;
            As[nb][lk + 2][lm] = pa0.z; As[nb][lk + 3][lm] = pa0.w;
            As[nb][lk + 4][lm] = pa1.x; As[nb][lk + 5][lm] = pa1.y;
            As[nb][lk + 6][lm] = pa1.z; As[nb][lk + 7][lm] = pa1.w;
            Bs[nb][lk + 0][lm] = pb0.x; Bs[nb][lk + 1][lm] = pb0.y;
            Bs[nb][lk + 2][lm] = pb0.z; Bs[nb][lk + 3][lm] = pb0.w;
            Bs[nb][lk + 4][lm] = pb1.x; Bs[nb][lk + 5][lm] = pb1.y;
            Bs[nb][lk + 6][lm] = pb1.z; Bs[nb][lk + 7][lm] = pb1.w;
            __syncthreads();
            buf = nb;
        }
    }

    const int c0 = col0 + tx * 8;
    float4 bv0 = *(const float4*)&bias[c0];
    float4 bv1 = *(const float4*)&bias[c0 + 4];
    #pragma unroll
    for (int i = 0; i < 8; i++) {
        int r = row0 + ty * 8 + i;
        float v0, v1, v2, v3, v4, v5, v6, v7;
        unpack2(acc[i][0], v0, v1); unpack2(acc[i][1], v2, v3);
        unpack2(acc[i][2], v4, v5); unpack2(acc[i][3], v6, v7);
        *(float4*)&C[(size_t)r * N + c0]     = make_float4(v0 + bv0.x, v1 + bv0.y, v2 + bv0.z, v3 + bv0.w);
        *(float4*)&C[(size_t)r * N + c0 + 4] = make_float4(v4 + bv1.x, v5 + bv1.y, v6 + bv1.z, v7 + bv1.w);
    }
}

// =====================================================================
// Scores+exp: attw[bh,q,k] = exp((Q·K)/8) (unnormalized) + row partials
// BK=16 double-buffered, K=64 (4 stages). Grid: (S/128, S/128, B*H)
// =====================================================================
__global__ __launch_bounds__(256) void scores_exp_kernel(float* __restrict__ attw)
{
    __shared__ float As[2][16][132];
    __shared__ float Bs[2][16][132];
    const int tid = threadIdx.x;
    const int tx = tid & 15, ty = tid >> 4;
    const int bh = blockIdx.z;
    const int b = bh >> 4, h = bh & 15;
    const int row0 = blockIdx.y * 128, col0 = blockIdx.x * 128;
    const int lm = tid >> 1;
    const int lk = (tid & 1) * 8;

    const float* Qp = g_qkv + (size_t)b * SS * E3 + h * DH + (size_t)(row0 + lm) * E3 + lk;
    const float* Kp = g_qkv + (size_t)b * SS * E3 + h * DH + EB + (size_t)(col0 + lm) * E3 + lk;

    u64 acc[8][4];
    #pragma unroll
    for (int i = 0; i < 8; i++)
        #pragma unroll
        for (int j = 0; j < 4; j++) acc[i][j] = 0ull;

    {
        float4 a0 = *(const float4*)(Qp);
        float4 a1 = *(const float4*)(Qp + 4);
        float4 b0 = *(const float4*)(Kp);
        float4 b1 = *(const float4*)(Kp + 4);
        As[0][lk + 0][lm] = a0.x; As[0][lk + 1][lm] = a0.y;
        As[0][lk + 2][lm] = a0.z; As[0][lk + 3][lm] = a0.w;
        As[0][lk + 4][lm] = a1.x; As[0][lk + 5][lm] = a1.y;
        As[0][lk + 6][lm] = a1.z; As[0][lk + 7][lm] = a1.w;
        Bs[0][lk + 0][lm] = b0.x; Bs[0][lk + 1][lm] = b0.y;
        Bs[0][lk + 2][lm] = b0.z; Bs[0][lk + 3][lm] = b0.w;
        Bs[0][lk + 4][lm] = b1.x; Bs[0][lk + 5][lm] = b1.y;
        Bs[0][lk + 6][lm] = b1.z; Bs[0][lk + 7][lm] = b1.w;
    }
    __syncthreads();

    int buf = 0;
    #pragma unroll
    for (int k0 = 0; k0 < DH; k0 += 16) {
        float4 pa0, pa1, pb0, pb1;
        const bool more = (k0 + 16 < DH);
        if (more) {
            pa0 = *(const float4*)(Qp + k0 + 16);
            pa1 = *(const float4*)(Qp + k0 + 20);
            pb0 = *(const float4*)(Kp + k0 + 16);
            pb1 = *(const float4*)(Kp + k0 + 20);
        }
        #pragma unroll
        for (int kk = 0; kk < 16; kk++) {
            float4 fa0 = *(const float4*)&As[buf][kk][ty * 8];
            float4 fa1 = *(const float4*)&As[buf][kk][ty * 8 + 4];
            float4 fb0 = *(const float4*)&Bs[buf][kk][tx * 8];
            float4 fb1 = *(const float4*)&Bs[buf][kk][tx * 8 + 4];
            float a[8] = {fa0.x, fa0.y, fa0.z, fa0.w, fa1.x, fa1.y, fa1.z, fa1.w};
            u64 bb[4] = {pack2(fb0.x, fb0.y), pack2(fb0.z, fb0.w),
                         pack2(fb1.x, fb1.y), pack2(fb1.z, fb1.w)};
            #pragma unroll
            for (int i = 0; i < 8; i++) {
                u64 ad = pack2(a[i], a[i]);
                #pragma unroll
                for (int j = 0; j < 4; j++) acc[i][j] = fma2(ad, bb[j], acc[i][j]);
            }
        }
        if (more) {
            int nb = buf ^ 1;
            As[nb][lk + 0][lm] = pa0.x; As[nb][lk + 1][lm] = pa0.y;
            As[nb][lk + 2][lm] = pa0.z; As[nb][lk + 3][lm] = pa0.w;
            As[nb][lk + 4][lm] = pa1.x; As[nb][lk + 5][lm] = pa1.y;
            As[nb][lk + 6][lm] = pa1.z; As[nb][lk + 7][lm] = pa1.w;
            Bs[nb][lk + 0][lm] = pb0.x; Bs[nb][lk + 1][lm] = pb0.y;
            Bs[nb][lk + 2][lm] = pb0.z; Bs[nb][lk + 3][lm] = pb0.w;
            Bs[nb][lk + 4][lm] = pb1.x; Bs[nb][lk + 5][lm] = pb1.y;
            Bs[nb][lk + 6][lm] = pb1.z; Bs[nb][lk + 7][lm] = pb1.w;
            __syncthreads();
            buf = nb;
        }
    }

    float* Cb = attw + (size_t)bh * SS * SS;
    const int c0 = col0 + tx * 8;
    #pragma unroll
    for (int i = 0; i < 8; i++) {
        int r = row0 + ty * 8 + i;
        float v[8];
        unpack2(acc[i][0], v[0], v[1]); unpack2(acc[i][1], v[2], v[3]);
        unpack2(acc[i][2], v[4], v[5]); unpack2(acc[i][3], v[6], v[7]);
        float rp = 0.0f;
        #pragma unroll
        for (int j = 0; j < 8; j++) { v[j] = __expf(v[j] * 0.125f); rp += v[j]; }
        *(float4*)&Cb[(size_t)r * SS + c0]     = make_float4(v[0], v[1], v[2], v[3]);
        *(float4*)&Cb[(size_t)r * SS + c0 + 4] = make_float4(v[4], v[5], v[6], v[7]);
        // deterministic half-warp reduction over tx (lanes 0-15 / 16-31)
        #pragma unroll
        for (int m = 1; m < 16; m <<= 1)
            rp += __shfl_xor_sync(0xffffffffu, rp, m);
        if (tx == 0)
            g_part[((size_t)bh * SS + r) * 16 + blockIdx.x] = rp;
    }
}

// =====================================================================
// Fold 16 col-block partials per row -> g_rowsum.
// =====================================================================
__global__ __launch_bounds__(256) void rowsum_fold_kernel()
{
    int row = blockIdx.x * 256 + threadIdx.x;
    const float* p = &g_part[(size_t)row * 16];
    float s = 0.0f;
    #pragma unroll
    for (int i = 0; i < 16; i++) s += p[i];
    g_rowsum[row] = s;
}

// =====================================================================
// Normalize: attw /= rowsum
// =====================================================================
__global__ __launch_bounds__(256) void norm_kernel(float* __restrict__ attw)
{
    size_t i4 = (size_t)blockIdx.x * 256 + threadIdx.x;
    size_t row = i4 >> 9;
    float inv = 1.0f / g_rowsum[row];
    float4* p = (float4*)attw;
    float4 v = p[i4];
    v.x *= inv; v.y *= inv; v.z *= inv; v.w *= inv;
    p[i4] = v;
}

// =====================================================================
// PV: g_attn[b,s,h*64+d] = sum_k P[bh,s,k] * V[bh,k,d]
// 128x64 tile, BK=16 double-buffered. Grid: (S/128, 1, B*H)
// =====================================================================
__global__ __launch_bounds__(256) void pv_kernel(const float* __restrict__ attw)
{
    __shared__ float As[2][16][132];
    __shared__ float Bs[2][16][68];
    const int tid = threadIdx.x;
    const int tx = tid & 7, ty = tid >> 3;
    const int bh = blockIdx.z;
    const int b = bh >> 4, h = bh & 15;
    const int row0 = blockIdx.x * 128;
    const int lm = tid >> 1;
    const int lk = (tid & 1) * 8;
    const int vr = tid >> 4;            // 0..15
    const int vc = (tid & 15) * 4;      // 0..60

    const float* Pp = attw + (size_t)bh * SS * SS + (size_t)(row0 + lm) * SS + lk;
    const float* Vp = g_qkv + (size_t)b * SS * E3 + 2 * EB + h * DH + (size_t)vr * E3 + vc;

    u64 acc[4][4];
    #pragma unroll
    for (int i = 0; i < 4; i++)
        #pragma unroll
        for (int j = 0; j < 4; j++) acc[i][j] = 0ull;

    {
        float4 a0 = *(const float4*)(Pp);
        float4 a1 = *(const float4*)(Pp + 4);
        float4 vv = *(const float4*)(Vp);
        As[0][lk + 0][lm] = a0.x; As[0][lk + 1][lm] = a0.y;
        As[0][lk + 2][lm] = a0.z; As[0][lk + 3][lm] = a0.w;
        As[0][lk + 4][lm] = a1.x; As[0][lk + 5][lm] = a1.y;
        As[0][lk + 6][lm] = a1.z; As[0][lk + 7][lm] = a1.w;
        *(float4*)&Bs[0][vr][vc] = vv;
    }
    __syncthreads();

    int buf = 0;
    for (int k0 = 0; k0 < SS; k0 += 16) {
        float4 pa0, pa1, pv0;
        const bool more = (k0 + 16 < SS);
        if (more) {
            pa0 = *(const float4*)(Pp + k0 + 16);
            pa1 = *(const float4*)(Pp + k0 + 20);
            pv0 = *(const float4*)(Vp + (size_t)(k0 + 16) * E3);
        }
        #pragma unroll
        for (int kk = 0; kk < 16; kk++) {
            float4 av = *(const float4*)&As[buf][kk][ty * 4];
            float4 fb0 = *(const float4*)&Bs[buf][kk][tx * 8];
            float4 fb1 = *(const float4*)&Bs[buf][kk][tx * 8 + 4];
            float a[4] = {av.x, av.y, av.z, av.w};
            u64 bb[4] = {pack2(fb0.x, fb0.y), pack2(fb0.z, fb0.w),
                         pack2(fb1.x, fb1.y), pack2(fb1.z, fb1.w)};
            #pragma unroll
            for (int i = 0; i < 4; i++) {
                u64 ad = pack2(a[i], a[i]);
                #pragma unroll
                for (int j = 0; j < 4; j++) acc[i][j] = fma2(ad, bb[j], acc[i][j]);
            }
        }
        if (more) {
            int nb = buf ^ 1;
            As[nb][lk + 0][lm] = pa0.x; As[nb][lk + 1][lm] = pa0.y;
            As[nb][lk + 2][lm] = pa0.z; As[nb][lk + 3][lm] = pa0.w;
            As[nb][lk + 4][lm] = pa1.x; As[nb][lk + 5][lm] = pa1.y;
            As[nb][lk + 6][lm] = pa1.z; As[nb][lk + 7][lm] = pa1.w;
            *(float4*)&Bs[nb][vr][vc] = pv0;
            __syncthreads();
            buf = nb;
        }
    }

    #pragma unroll
    for (int i = 0; i < 4; i++) {
        int s = row0 + ty * 4 + i;
        float v0, v1, v2, v3, v4, v5, v6, v7;
        unpack2(acc[i][0], v0, v1); unpack2(acc[i][1], v2, v3);
        unpack2(acc[i][2], v4, v5); unpack2(acc[i][3], v6, v7);
        float* o = &g_attn[(size_t)(b * SS + s) * EB + h * DH + tx * 8];
        *(float4*)&o[0] = make_float4(v0, v1, v2, v3);
        *(float4*)&o[4] = make_float4(v4, v5, v6, v7);
    }
}

// =====================================================================
extern "C" void kernel_launch(void* const* d_in, const int* in_sizes, int n_in,
                              void* d_out, int out_size)
{
    (void)in_sizes; (void)n_in; (void)out_size;
    const float* x     = (const float*)d_in[0];
    const float* qkv_w = (const float*)d_in[1];
    const float* qkv_b = (const float*)d_in[2];
    const float* out_w = (const float*)d_in[3];
    const float* out_b = (const float*)d_in[4];

    float* out  = (float*)d_out;                  // output: [2,2048,1024]
    float* attw = out + (size_t)MT * EB;          // attn_weights: [2,16,2048,2048]

    // Resolve true DEVICE addresses of __device__ globals (host shadow
    // symbols are silently dereferenced via ATS on GB300 otherwise).
    float* d_qkv  = nullptr;
    float* d_attn = nullptr;
    cudaGetSymbolAddress((void**)&d_qkv,  g_qkv);
    cudaGetSymbolAddress((void**)&d_attn, g_attn);

    // 1. QKV projection
    {
        dim3 grid(E3 / 128, MT / 128);
        sgemm_bias_nt<<<grid, 256>>>(x, qkv_w, qkv_b, d_qkv, MT, E3, EB);
    }
    // 2. scores + exp + row partials
    {
        dim3 grid(SS / 128, SS / 128, BB * HN);
        scores_exp_kernel<<<grid, 256>>>(attw);
    }
    // 3. fold partials
    rowsum_fold_kernel<<<BB * HN * SS / 256, 256>>>();
    // 4. normalize
    {
        size_t n4 = (size_t)BB * HN * SS * SS / 4;
        norm_kernel<<<(unsigned)(n4 / 256), 256>>>(attw);
    }
    // 5. P @ V
    {
        dim3 grid(SS / 128, 1, BB * HN);
        pv_kernel<<<grid, 256>>>(attw);
    }
    // 6. out projection
    {
        dim3 grid(EB / 128, MT / 128);
        sgemm_bias_nt<<<grid, 256>>>(d_attn, out_w, out_b, out, MT, EB, EB);
    }
}

// round 10
// speedup vs baseline: 1.5993x; 1.1865x over previous
#include <cuda_runtime.h>
#include <cuda_bf16.h>
#include <cstdint>

#define EB    1024
#define HN    16
#define DH    64
#define BB    2
#define SS    2048
#define MT    (BB*SS)       // 4096
#define E3    (3*EB)        // 3072

typedef unsigned long long u64;

// Scratch (device globals — allocation is forbidden)
__device__ float g_qkv[(size_t)MT * E3];      // [token][3E]
__device__ float g_attn[(size_t)MT * EB];     // [token][E]
__device__ float g_rowsum[BB * HN * SS];
__device__ float g_part[(size_t)BB * HN * SS * 16];

// ---------------- packed f32x2 helpers (B300 FFMA2) ----------------
__device__ __forceinline__ u64 pack2(float x, float y) {
    u64 r;
    asm("mov.b64 %0, {%1, %2};" : "=l"(r) : "r"(__float_as_uint(x)), "r"(__float_as_uint(y)));
    return r;
}
__device__ __forceinline__ void unpack2(u64 v, float& x, float& y) {
    unsigned lo, hi;
    asm("mov.b64 {%0, %1}, %2;" : "=r"(lo), "=r"(hi) : "l"(v));
    x = __uint_as_float(lo); y = __uint_as_float(hi);
}
__device__ __forceinline__ u64 fma2(u64 a, u64 b, u64 c) {
    u64 d;
    asm("fma.rn.f32x2 %0, %1, %2, %3;" : "=l"(d) : "l"(a), "l"(b), "l"(c));
    return d;
}

// ---------------- HMMA (mma.sync) helpers — sm_80-era PTX ----------------
__device__ __forceinline__ uint32_t smem_u32(const void* p) {
    uint32_t a;
    asm("{ .reg .u64 t; cvta.to.shared.u64 t, %1; cvt.u32.u64 %0, t; }" : "=r"(a) : "l"(p));
    return a;
}
#define LDSM_X4(r, addr) \
    asm volatile("ldmatrix.sync.aligned.m8n8.x4.shared.b16 {%0,%1,%2,%3}, [%4];" \
        : "=r"((r)[0]), "=r"((r)[1]), "=r"((r)[2]), "=r"((r)[3]) : "r"(addr))
#define LDSM_X2(r, addr) \
    asm volatile("ldmatrix.sync.aligned.m8n8.x2.shared.b16 {%0,%1}, [%2];" \
        : "=r"((r)[0]), "=r"((r)[1]) : "r"(addr))
#define MMA_BF16(d, a, b) \
    asm volatile("mma.sync.aligned.m16n8k16.row.col.f32.bf16.bf16.f32 " \
        "{%0,%1,%2,%3}, {%4,%5,%6,%7}, {%8,%9}, {%0,%1,%2,%3};" \
        : "+f"((d)[0]), "+f"((d)[1]), "+f"((d)[2]), "+f"((d)[3]) \
        : "r"((a)[0]), "r"((a)[1]), "r"((a)[2]), "r"((a)[3]), \
          "r"((b)[0]), "r"((b)[1]))

// split two fp32 into bf16-hi pair and bf16-lo pair (packed u32: lo half = x0)
__device__ __forceinline__ void split2(float x0, float x1, uint32_t& hi2, uint32_t& lo2) {
    asm("cvt.rn.bf16x2.f32 %0, %1, %2;" : "=r"(hi2) : "f"(x1), "f"(x0));
    float h0 = __uint_as_float(hi2 << 16);
    float h1 = __uint_as_float(hi2 & 0xFFFF0000u);
    float r0 = x0 - h0, r1 = x1 - h1;
    asm("cvt.rn.bf16x2.f32 %0, %1, %2;" : "=r"(lo2) : "f"(r1), "f"(r0));
}

// =====================================================================
// HMMA GEMM: C[M,N] = A[M,K] @ B[N,K]^T + bias[N], fp32 via bf16 split
// (hi*hi + hi*lo + lo*hi), fp32 accumulate. CTA 128x128, BK=32.
// 8 warps (2m x 4n), warp tile 64x32 of m16n8k16 atoms.
// =====================================================================
__global__ __launch_bounds__(256) void mma_gemm_bias_nt(
    const float* __restrict__ A, const float* __restrict__ B,
    const float* __restrict__ bias, float* __restrict__ C,
    int M, int N, int K)
{
    __shared__ __align__(16) uint16_t Ah[128][40];   // 80B rows: 16B-aligned,
    __shared__ __align__(16) uint16_t Al[128][40];   // conflict-free ldmatrix
    __shared__ __align__(16) uint16_t Bh[128][40];
    __shared__ __align__(16) uint16_t Bl[128][40];

    const int tid = threadIdx.x;
    const int lane = tid & 31, wid = tid >> 5;
    const int warp_m = wid >> 2, warp_n = wid & 3;        // 2 x 4
    const int row0 = blockIdx.y * 128, col0 = blockIdx.x * 128;

    float acc[4][4][4];
    #pragma unroll
    for (int mi = 0; mi < 4; mi++)
        #pragma unroll
        for (int ni = 0; ni < 4; ni++)
            #pragma unroll
            for (int f = 0; f < 4; f++) acc[mi][ni][f] = 0.0f;

    for (int k0 = 0; k0 < K; k0 += 32) {
        // global -> split -> smem (128x32 fp32 each for A,B)
        #pragma unroll
        for (int i = 0; i < 4; i++) {
            int idx = tid + i * 256;         // 0..1023 float4 units
            int r = idx >> 3, c4 = idx & 7;  // row 0..127, float4-col 0..7
            float4 va = *(const float4*)&A[(size_t)(row0 + r) * K + k0 + c4 * 4];
            uint32_t h0, l0, h1, l1;
            split2(va.x, va.y, h0, l0); split2(va.z, va.w, h1, l1);
            *(uint32_t*)&Ah[r][c4 * 4]     = h0; *(uint32_t*)&Ah[r][c4 * 4 + 2] = h1;
            *(uint32_t*)&Al[r][c4 * 4]     = l0; *(uint32_t*)&Al[r][c4 * 4 + 2] = l1;
            float4 vb = *(const float4*)&B[(size_t)(col0 + r) * K + k0 + c4 * 4];
            split2(vb.x, vb.y, h0, l0); split2(vb.z, vb.w, h1, l1);
            *(uint32_t*)&Bh[r][c4 * 4]     = h0; *(uint32_t*)&Bh[r][c4 * 4 + 2] = h1;
            *(uint32_t*)&Bl[r][c4 * 4]     = l0; *(uint32_t*)&Bl[r][c4 * 4 + 2] = l1;
        }
        __syncthreads();

        #pragma unroll
        for (int ks = 0; ks < 2; ks++) {
            // A fragments (x4 ldmatrix): lanes 0-15 -> k-low half, 16-31 -> k-high
            const int ka = ks * 16 + ((lane >> 4) << 3);
            uint32_t ah[4][4], al_[4][4];
            #pragma unroll
            for (int mi = 0; mi < 4; mi++) {
                int r = warp_m * 64 + mi * 16 + (lane & 15);
                LDSM_X4(ah[mi],  smem_u32(&Ah[r][ka]));
                LDSM_X4(al_[mi], smem_u32(&Al[r][ka]));
            }
            // B fragments (x2 ldmatrix): lanes 0-7 -> k0, 8-15 -> k+8
            const int kb = ks * 16 + ((lane >> 3) & 1) * 8;
            uint32_t bh[4][2], bl_[4][2];
            #pragma unroll
            for (int ni = 0; ni < 4; ni++) {
                int r = warp_n * 32 + ni * 8 + (lane & 7);
                LDSM_X2(bh[ni],  smem_u32(&Bh[r][kb]));
                LDSM_X2(bl_[ni], smem_u32(&Bl[r][kb]));
            }
            #pragma unroll
            for (int mi = 0; mi < 4; mi++)
                #pragma unroll
                for (int ni = 0; ni < 4; ni++) {
                    MMA_BF16(acc[mi][ni], ah[mi],  bh[ni]);
                    MMA_BF16(acc[mi][ni], ah[mi],  bl_[ni]);
                    MMA_BF16(acc[mi][ni], al_[mi], bh[ni]);
                }
        }
        __syncthreads();
    }

    // epilogue: thread t holds D rows (t/4, t/4+8), cols (t%4)*2, +1
    #pragma unroll
    for (int mi = 0; mi < 4; mi++) {
        int r0 = row0 + warp_m * 64 + mi * 16 + (lane >> 2);
        #pragma unroll
        for (int ni = 0; ni < 4; ni++) {
            int c = col0 + warp_n * 32 + ni * 8 + (lane & 3) * 2;
            float2 bv = *(const float2*)&bias[c];
            *(float2*)&C[(size_t)r0 * N + c] =
                make_float2(acc[mi][ni][0] + bv.x, acc[mi][ni][1] + bv.y);
            *(float2*)&C[(size_t)(r0 + 8) * N + c] =
                make_float2(acc[mi][ni][2] + bv.x, acc[mi][ni][3] + bv.y);
        }
    }
}

// =====================================================================
// Scores+exp (FFMA2, double-buffered) — proven round-6 path
// =====================================================================
__global__ __launch_bounds__(256) void scores_exp_kernel(float* __restrict__ attw)
{
    __shared__ float As[2][16][132];
    __shared__ float Bs[2][16][132];
    const int tid = threadIdx.x;
    const int tx = tid & 15, ty = tid >> 4;
    const int bh = blockIdx.z;
    const int b = bh >> 4, h = bh & 15;
    const int row0 = blockIdx.y * 128, col0 = blockIdx.x * 128;
    const int lm = tid >> 1;
    const int lk = (tid & 1) * 8;

    const float* Qp = g_qkv + (size_t)b * SS * E3 + h * DH + (size_t)(row0 + lm) * E3 + lk;
    const float* Kp = g_qkv + (size_t)b * SS * E3 + h * DH + EB + (size_t)(col0 + lm) * E3 + lk;

    u64 acc[8][4];
    #pragma unroll
    for (int i = 0; i < 8; i++)
        #pragma unroll
        for (int j = 0; j < 4; j++) acc[i][j] = 0ull;

    {
        float4 a0 = *(const float4*)(Qp);
        float4 a1 = *(const float4*)(Qp + 4);
        float4 b0 = *(const float4*)(Kp);
        float4 b1 = *(const float4*)(Kp + 4);
        As[0][lk + 0][lm] = a0.x; As[0][lk + 1][lm] = a0.y;
        As[0][lk + 2][lm] = a0.z; As[0][lk + 3][lm] = a0.w;
        As[0][lk + 4][lm] = a1.x; As[0][lk + 5][lm] = a1.y;
        As[0][lk + 6][lm] = a1.z; As[0][lk + 7][lm] = a1.w;
        Bs[0][lk + 0][lm] = b0.x; Bs[0][lk + 1][lm] = b0.y;
        Bs[0][lk + 2][lm] = b0.z; Bs[0][lk + 3][lm] = b0.w;
        Bs[0][lk + 4][lm] = b1.x; Bs[0][lk + 5][lm] = b1.y;
        Bs[0][lk + 6][lm] = b1.z; Bs[0][lk + 7][lm] = b1.w;
    }
    __syncthreads();

    int buf = 0;
    #pragma unroll
    for (int k0 = 0; k0 < DH; k0 += 16) {
        float4 pa0, pa1, pb0, pb1;
        const bool more = (k0 + 16 < DH);
        if (more) {
            pa0 = *(const float4*)(Qp + k0 + 16);
            pa1 = *(const float4*)(Qp + k0 + 20);
            pb0 = *(const float4*)(Kp + k0 + 16);
            pb1 = *(const float4*)(Kp + k0 + 20);
        }
        #pragma unroll
        for (int kk = 0; kk < 16; kk++) {
            float4 fa0 = *(const float4*)&As[buf][kk][ty * 8];
            float4 fa1 = *(const float4*)&As[buf][kk][ty * 8 + 4];
            float4 fb0 = *(const float4*)&Bs[buf][kk][tx * 8];
            float4 fb1 = *(const float4*)&Bs[buf][kk][tx * 8 + 4];
            float a[8] = {fa0.x, fa0.y, fa0.z, fa0.w, fa1.x, fa1.y, fa1.z, fa1.w};
            u64 bb[4] = {pack2(fb0.x, fb0.y), pack2(fb0.z, fb0.w),
                         pack2(fb1.x, fb1.y), pack2(fb1.z, fb1.w)};
            #pragma unroll
            for (int i = 0; i < 8; i++) {
                u64 ad = pack2(a[i], a[i]);
                #pragma unroll
                for (int j = 0; j < 4; j++) acc[i][j] = fma2(ad, bb[j], acc[i][j]);
            }
        }
        if (more) {
            int nb = buf ^ 1;
            As[nb][lk + 0][lm] = pa0.x; As[nb][lk + 1][lm] = pa0.y;
            As[nb][lk + 2][lm] = pa0.z; As[nb][lk + 3][lm] = pa0.w;
            As[nb][lk + 4][lm] = pa1.x; As[nb][lk + 5][lm] = pa1.y;
            As[nb][lk + 6][lm] = pa1.z; As[nb][lk + 7][lm] = pa1.w;
            Bs[nb][lk + 0][lm] = pb0.x; Bs[nb][lk + 1][lm] = pb0.y;
            Bs[nb][lk + 2][lm] = pb0.z; Bs[nb][lk + 3][lm] = pb0.w;
            Bs[nb][lk + 4][lm] = pb1.x; Bs[nb][lk + 5][lm] = pb1.y;
            Bs[nb][lk + 6][lm] = pb1.z; Bs[nb][lk + 7][lm] = pb1.w;
            __syncthreads();
            buf = nb;
        }
    }

    float* Cb = attw + (size_t)bh * SS * SS;
    const int c0 = col0 + tx * 8;
    #pragma unroll
    for (int i = 0; i < 8; i++) {
        int r = row0 + ty * 8 + i;
        float v[8];
        unpack2(acc[i][0], v[0], v[1]); unpack2(acc[i][1], v[2], v[3]);
        unpack2(acc[i][2], v[4], v[5]); unpack2(acc[i][3], v[6], v[7]);
        float rp = 0.0f;
        #pragma unroll
        for (int j = 0; j < 8; j++) { v[j] = __expf(v[j] * 0.125f); rp += v[j]; }
        *(float4*)&Cb[(size_t)r * SS + c0]     = make_float4(v[0], v[1], v[2], v[3]);
        *(float4*)&Cb[(size_t)r * SS + c0 + 4] = make_float4(v[4], v[5], v[6], v[7]);
        #pragma unroll
        for (int m = 1; m < 16; m <<= 1)
            rp += __shfl_xor_sync(0xffffffffu, rp, m);
        if (tx == 0)
            g_part[((size_t)bh * SS + r) * 16 + blockIdx.x] = rp;
    }
}

__global__ __launch_bounds__(256) void rowsum_fold_kernel()
{
    int row = blockIdx.x * 256 + threadIdx.x;
    const float* p = &g_part[(size_t)row * 16];
    float s = 0.0f;
    #pragma unroll
    for (int i = 0; i < 16; i++) s += p[i];
    g_rowsum[row] = s;
}

__global__ __launch_bounds__(256) void norm_kernel(float* __restrict__ attw)
{
    size_t i4 = (size_t)blockIdx.x * 256 + threadIdx.x;
    size_t row = i4 >> 9;
    float inv = 1.0f / g_rowsum[row];
    float4* p = (float4*)attw;
    float4 v = p[i4];
    v.x *= inv; v.y *= inv; v.z *= inv; v.w *= inv;
    p[i4] = v;
}

// =====================================================================
// PV (FFMA2, double-buffered) — proven round-6 path
// =====================================================================
__global__ __launch_bounds__(256) void pv_kernel(const float* __restrict__ attw)
{
    __shared__ float As[2][16][132];
    __shared__ float Bs[2][16][68];
    const int tid = threadIdx.x;
    const int tx = tid & 7, ty = tid >> 3;
    const int bh = blockIdx.z;
    const int b = bh >> 4, h = bh & 15;
    const int row0 = blockIdx.x * 128;
    const int lm = tid >> 1;
    const int lk = (tid & 1) * 8;
    const int vr = tid >> 4;
    const int vc = (tid & 15) * 4;

    const float* Pp = attw + (size_t)bh * SS * SS + (size_t)(row0 + lm) * SS + lk;
    const float* Vp = g_qkv + (size_t)b * SS * E3 + 2 * EB + h * DH + (size_t)vr * E3 + vc;

    u64 acc[4][4];
    #pragma unroll
    for (int i = 0; i < 4; i++)
        #pragma unroll
        for (int j = 0; j < 4; j++) acc[i][j] = 0ull;

    {
        float4 a0 = *(const float4*)(Pp);
        float4 a1 = *(const float4*)(Pp + 4);
        float4 vv = *(const float4*)(Vp);
        As[0][lk + 0][lm] = a0.x; As[0][lk + 1][lm] = a0.y;
        As[0][lk + 2][lm] = a0.z; As[0][lk + 3][lm] = a0.w;
        As[0][lk + 4][lm] = a1.x; As[0][lk + 5][lm] = a1.y;
        As[0][lk + 6][lm] = a1.z; As[0][lk + 7][lm] = a1.w;
        *(float4*)&Bs[0][vr][vc] = vv;
    }
    __syncthreads();

    int buf = 0;
    for (int k0 = 0; k0 < SS; k0 += 16) {
        float4 pa0, pa1, pv0;
        const bool more = (k0 + 16 < SS);
        if (more) {
            pa0 = *(const float4*)(Pp + k0 + 16);
            pa1 = *(const float4*)(Pp + k0 + 20);
            pv0 = *(const float4*)(Vp + (size_t)(k0 + 16) * E3);
        }
        #pragma unroll
        for (int kk = 0; kk < 16; kk++) {
            float4 av = *(const float4*)&As[buf][kk][ty * 4];
            float4 fb0 = *(const float4*)&Bs[buf][kk][tx * 8];
            float4 fb1 = *(const float4*)&Bs[buf][kk][tx * 8 + 4];
            float a[4] = {av.x, av.y, av.z, av.w};
            u64 bb[4] = {pack2(fb0.x, fb0.y), pack2(fb0.z, fb0.w),
                         pack2(fb1.x, fb1.y), pack2(fb1.z, fb1.w)};
            #pragma unroll
            for (int i = 0; i < 4; i++) {
                u64 ad = pack2(a[i], a[i]);
                #pragma unroll
                for (int j = 0; j < 4; j++) acc[i][j] = fma2(ad, bb[j], acc[i][j]);
            }
        }
        if (more) {
            int nb = buf ^ 1;
            As[nb][lk + 0][lm] = pa0.x; As[nb][lk + 1][lm] = pa0.y;
            As[nb][lk + 2][lm] = pa0.z; As[nb][lk + 3][lm] = pa0.w;
            As[nb][lk + 4][lm] = pa1.x; As[nb][lk + 5][lm] = pa1.y;
            As[nb][lk + 6][lm] = pa1.z; As[nb][lk + 7][lm] = pa1.w;
            *(float4*)&Bs[nb][vr][vc] = pv0;
            __syncthreads();
            buf = nb;
        }
    }

    #pragma unroll
    for (int i = 0; i < 4; i++) {
        int s = row0 + ty * 4 + i;
        float v0, v1, v2, v3, v4, v5, v6, v7;
        unpack2(acc[i][0], v0, v1); unpack2(acc[i][1], v2, v3);
        unpack2(acc[i][2], v4, v5); unpack2(acc[i][3], v6, v7);
        float* o = &g_attn[(size_t)(b * SS + s) * EB + h * DH + tx * 8];
        *(float4*)&o[0] = make_float4(v0, v1, v2, v3);
        *(float4*)&o[4] = make_float4(v4, v5, v6, v7);
    }
}

// =====================================================================
extern "C" void kernel_launch(void* const* d_in, const int* in_sizes, int n_in,
                              void* d_out, int out_size)
{
    (void)in_sizes; (void)n_in; (void)out_size;
    const float* x     = (const float*)d_in[0];
    const float* qkv_w = (const float*)d_in[1];
    const float* qkv_b = (const float*)d_in[2];
    const float* out_w = (const float*)d_in[3];
    const float* out_b = (const float*)d_in[4];

    float* out  = (float*)d_out;                  // output: [2,2048,1024]
    float* attw = out + (size_t)MT * EB;          // attn_weights: [2,16,2048,2048]

    float* d_qkv  = nullptr;
    float* d_attn = nullptr;
    cudaGetSymbolAddress((void**)&d_qkv,  g_qkv);
    cudaGetSymbolAddress((void**)&d_attn, g_attn);

    // 1. QKV projection (HMMA bf16 3-way split)
    {
        dim3 grid(E3 / 128, MT / 128);
        mma_gemm_bias_nt<<<grid, 256>>>(x, qkv_w, qkv_b, d_qkv, MT, E3, EB);
    }
    // 2. scores + exp + row partials
    {
        dim3 grid(SS / 128, SS / 128, BB * HN);
        scores_exp_kernel<<<grid, 256>>>(attw);
    }
    // 3. fold partials
    rowsum_fold_kernel<<<BB * HN * SS / 256, 256>>>();
    // 4. normalize
    {
        size_t n4 = (size_t)BB * HN * SS * SS / 4;
        norm_kernel<<<(unsigned)(n4 / 256), 256>>>(attw);
    }
    // 5. P @ V
    {
        dim3 grid(SS / 128, 1, BB * HN);
        pv_kernel<<<grid, 256>>>(attw);
    }
    // 6. out projection (HMMA bf16 3-way split)
    {
        dim3 grid(EB / 128, MT / 128);
        mma_gemm_bias_nt<<<grid, 256>>>(d_attn, out_w, out_b, out, MT, EB, EB);
    }
}

// round 11
// speedup vs baseline: 2.2202x; 1.3882x over previous
#include <cuda_runtime.h>
#include <cuda_bf16.h>
#include <cstdint>

#define EB    1024
#define HN    16
#define DH    64
#define BB    2
#define SS    2048
#define MT    (BB*SS)       // 4096
#define E3    (3*EB)        // 3072

typedef unsigned long long u64;

// Scratch (device globals — allocation is forbidden)
__device__ float g_qkv[(size_t)MT * E3];      // [token][3E]
__device__ float g_attn[(size_t)MT * EB];     // [token][E]
__device__ float g_rowsum[BB * HN * SS];
__device__ float g_part[(size_t)BB * HN * SS * 16];

// ---------------- HMMA (mma.sync) helpers — sm_80-era PTX ----------------
__device__ __forceinline__ uint32_t smem_u32(const void* p) {
    uint32_t a;
    asm("{ .reg .u64 t; cvta.to.shared.u64 t, %1; cvt.u32.u64 %0, t; }" : "=r"(a) : "l"(p));
    return a;
}
#define LDSM_X4(r, addr) \
    asm volatile("ldmatrix.sync.aligned.m8n8.x4.shared.b16 {%0,%1,%2,%3}, [%4];" \
        : "=r"((r)[0]), "=r"((r)[1]), "=r"((r)[2]), "=r"((r)[3]) : "r"(addr))
#define LDSM_X2(r, addr) \
    asm volatile("ldmatrix.sync.aligned.m8n8.x2.shared.b16 {%0,%1}, [%2];" \
        : "=r"((r)[0]), "=r"((r)[1]) : "r"(addr))
#define LDSM_X2_TRANS(r, addr) \
    asm volatile("ldmatrix.sync.aligned.m8n8.x2.trans.shared.b16 {%0,%1}, [%2];" \
        : "=r"((r)[0]), "=r"((r)[1]) : "r"(addr))
#define MMA_BF16(d, a, b) \
    asm volatile("mma.sync.aligned.m16n8k16.row.col.f32.bf16.bf16.f32 " \
        "{%0,%1,%2,%3}, {%4,%5,%6,%7}, {%8,%9}, {%0,%1,%2,%3};" \
        : "+f"((d)[0]), "+f"((d)[1]), "+f"((d)[2]), "+f"((d)[3]) \
        : "r"((a)[0]), "r"((a)[1]), "r"((a)[2]), "r"((a)[3]), \
          "r"((b)[0]), "r"((b)[1]))

// split two fp32 into bf16-hi pair and bf16-lo pair (packed u32: lo half = x0)
__device__ __forceinline__ void split2(float x0, float x1, uint32_t& hi2, uint32_t& lo2) {
    asm("cvt.rn.bf16x2.f32 %0, %1, %2;" : "=r"(hi2) : "f"(x1), "f"(x0));
    float h0 = __uint_as_float(hi2 << 16);
    float h1 = __uint_as_float(hi2 & 0xFFFF0000u);
    float r0 = x0 - h0, r1 = x1 - h1;
    asm("cvt.rn.bf16x2.f32 %0, %1, %2;" : "=r"(lo2) : "f"(r1), "f"(r0));
}

// =====================================================================
// HMMA GEMM: C[M,N] = A[M,K] @ B[N,K]^T + bias[N]  (proven round-10)
// CTA 128x128, BK=32, 8 warps (2m x 4n), warp tile 64x32.
// =====================================================================
__global__ __launch_bounds__(256) void mma_gemm_bias_nt(
    const float* __restrict__ A, const float* __restrict__ B,
    const float* __restrict__ bias, float* __restrict__ C,
    int M, int N, int K)
{
    __shared__ __align__(16) uint16_t Ah[128][40];
    __shared__ __align__(16) uint16_t Al[128][40];
    __shared__ __align__(16) uint16_t Bh[128][40];
    __shared__ __align__(16) uint16_t Bl[128][40];

    const int tid = threadIdx.x;
    const int lane = tid & 31, wid = tid >> 5;
    const int warp_m = wid >> 2, warp_n = wid & 3;
    const int row0 = blockIdx.y * 128, col0 = blockIdx.x * 128;

    float acc[4][4][4];
    #pragma unroll
    for (int mi = 0; mi < 4; mi++)
        #pragma unroll
        for (int ni = 0; ni < 4; ni++)
            #pragma unroll
            for (int f = 0; f < 4; f++) acc[mi][ni][f] = 0.0f;

    for (int k0 = 0; k0 < K; k0 += 32) {
        #pragma unroll
        for (int i = 0; i < 4; i++) {
            int idx = tid + i * 256;
            int r = idx >> 3, c4 = idx & 7;
            float4 va = *(const float4*)&A[(size_t)(row0 + r) * K + k0 + c4 * 4];
            uint32_t h0, l0, h1, l1;
            split2(va.x, va.y, h0, l0); split2(va.z, va.w, h1, l1);
            *(uint32_t*)&Ah[r][c4 * 4]     = h0; *(uint32_t*)&Ah[r][c4 * 4 + 2] = h1;
            *(uint32_t*)&Al[r][c4 * 4]     = l0; *(uint32_t*)&Al[r][c4 * 4 + 2] = l1;
            float4 vb = *(const float4*)&B[(size_t)(col0 + r) * K + k0 + c4 * 4];
            split2(vb.x, vb.y, h0, l0); split2(vb.z, vb.w, h1, l1);
            *(uint32_t*)&Bh[r][c4 * 4]     = h0; *(uint32_t*)&Bh[r][c4 * 4 + 2] = h1;
            *(uint32_t*)&Bl[r][c4 * 4]     = l0; *(uint32_t*)&Bl[r][c4 * 4 + 2] = l1;
        }
        __syncthreads();

        #pragma unroll
        for (int ks = 0; ks < 2; ks++) {
            const int ka = ks * 16 + ((lane >> 4) << 3);
            uint32_t ah[4][4], al_[4][4];
            #pragma unroll
            for (int mi = 0; mi < 4; mi++) {
                int r = warp_m * 64 + mi * 16 + (lane & 15);
                LDSM_X4(ah[mi],  smem_u32(&Ah[r][ka]));
                LDSM_X4(al_[mi], smem_u32(&Al[r][ka]));
            }
            const int kb = ks * 16 + ((lane >> 3) & 1) * 8;
            uint32_t bh[4][2], bl_[4][2];
            #pragma unroll
            for (int ni = 0; ni < 4; ni++) {
                int r = warp_n * 32 + ni * 8 + (lane & 7);
                LDSM_X2(bh[ni],  smem_u32(&Bh[r][kb]));
                LDSM_X2(bl_[ni], smem_u32(&Bl[r][kb]));
            }
            #pragma unroll
            for (int mi = 0; mi < 4; mi++)
                #pragma unroll
                for (int ni = 0; ni < 4; ni++) {
                    MMA_BF16(acc[mi][ni], ah[mi],  bh[ni]);
                    MMA_BF16(acc[mi][ni], ah[mi],  bl_[ni]);
                    MMA_BF16(acc[mi][ni], al_[mi], bh[ni]);
                }
        }
        __syncthreads();
    }

    #pragma unroll
    for (int mi = 0; mi < 4; mi++) {
        int r0 = row0 + warp_m * 64 + mi * 16 + (lane >> 2);
        #pragma unroll
        for (int ni = 0; ni < 4; ni++) {
            int c = col0 + warp_n * 32 + ni * 8 + (lane & 3) * 2;
            float2 bv = *(const float2*)&bias[c];
            *(float2*)&C[(size_t)r0 * N + c] =
                make_float2(acc[mi][ni][0] + bv.x, acc[mi][ni][1] + bv.y);
            *(float2*)&C[(size_t)(r0 + 8) * N + c] =
                make_float2(acc[mi][ni][2] + bv.x, acc[mi][ni][3] + bv.y);
        }
    }
}

// =====================================================================
// Scores (HMMA): attw[bh,q,k] = exp((Q·K)/8) unnormalized + row partials
// Same mainloop as gemm (A=Q, B=K, row stride E3, K=64 -> 2 chunks).
// Grid: (16, 16, 32)
// =====================================================================
__global__ __launch_bounds__(256) void mma_scores_kernel(float* __restrict__ attw)
{
    __shared__ __align__(16) uint16_t Ah[128][40];
    __shared__ __align__(16) uint16_t Al[128][40];
    __shared__ __align__(16) uint16_t Bh[128][40];
    __shared__ __align__(16) uint16_t Bl[128][40];
    __shared__ float s_red[128][4];

    const int tid = threadIdx.x;
    const int lane = tid & 31, wid = tid >> 5;
    const int warp_m = wid >> 2, warp_n = wid & 3;
    const int bh = blockIdx.z;
    const int b = bh >> 4, h = bh & 15;
    const int row0 = blockIdx.y * 128, col0 = blockIdx.x * 128;

    const float* Qb = g_qkv + (size_t)b * SS * E3 + h * DH;
    const float* Kb = Qb + EB;

    float acc[4][4][4];
    #pragma unroll
    for (int mi = 0; mi < 4; mi++)
        #pragma unroll
        for (int ni = 0; ni < 4; ni++)
            #pragma unroll
            for (int f = 0; f < 4; f++) acc[mi][ni][f] = 0.0f;

    #pragma unroll
    for (int k0 = 0; k0 < DH; k0 += 32) {
        #pragma unroll
        for (int i = 0; i < 4; i++) {
            int idx = tid + i * 256;
            int r = idx >> 3, c4 = idx & 7;
            float4 va = *(const float4*)&Qb[(size_t)(row0 + r) * E3 + k0 + c4 * 4];
            uint32_t h0, l0, h1, l1;
            split2(va.x, va.y, h0, l0); split2(va.z, va.w, h1, l1);
            *(uint32_t*)&Ah[r][c4 * 4]     = h0; *(uint32_t*)&Ah[r][c4 * 4 + 2] = h1;
            *(uint32_t*)&Al[r][c4 * 4]     = l0; *(uint32_t*)&Al[r][c4 * 4 + 2] = l1;
            float4 vb = *(const float4*)&Kb[(size_t)(col0 + r) * E3 + k0 + c4 * 4];
            split2(vb.x, vb.y, h0, l0); split2(vb.z, vb.w, h1, l1);
            *(uint32_t*)&Bh[r][c4 * 4]     = h0; *(uint32_t*)&Bh[r][c4 * 4 + 2] = h1;
            *(uint32_t*)&Bl[r][c4 * 4]     = l0; *(uint32_t*)&Bl[r][c4 * 4 + 2] = l1;
        }
        __syncthreads();

        #pragma unroll
        for (int ks = 0; ks < 2; ks++) {
            const int ka = ks * 16 + ((lane >> 4) << 3);
            uint32_t ah[4][4], al_[4][4];
            #pragma unroll
            for (int mi = 0; mi < 4; mi++) {
                int r = warp_m * 64 + mi * 16 + (lane & 15);
                LDSM_X4(ah[mi],  smem_u32(&Ah[r][ka]));
                LDSM_X4(al_[mi], smem_u32(&Al[r][ka]));
            }
            const int kb = ks * 16 + ((lane >> 3) & 1) * 8;
            uint32_t bh[4][2], bl_[4][2];
            #pragma unroll
            for (int ni = 0; ni < 4; ni++) {
                int r = warp_n * 32 + ni * 8 + (lane & 7);
                LDSM_X2(bh[ni],  smem_u32(&Bh[r][kb]));
                LDSM_X2(bl_[ni], smem_u32(&Bl[r][kb]));
            }
            #pragma unroll
            for (int mi = 0; mi < 4; mi++)
                #pragma unroll
                for (int ni = 0; ni < 4; ni++) {
                    MMA_BF16(acc[mi][ni], ah[mi],  bh[ni]);
                    MMA_BF16(acc[mi][ni], ah[mi],  bl_[ni]);
                    MMA_BF16(acc[mi][ni], al_[mi], bh[ni]);
                }
        }
        __syncthreads();
    }

    // epilogue: exp, store, rowsum partials
    float* Cb = attw + (size_t)bh * SS * SS;
    #pragma unroll
    for (int mi = 0; mi < 4; mi++) {
        int rl = warp_m * 64 + mi * 16 + (lane >> 2);   // local row (lo)
        float p_lo = 0.0f, p_hi = 0.0f;
        #pragma unroll
        for (int ni = 0; ni < 4; ni++) {
            int c = col0 + warp_n * 32 + ni * 8 + (lane & 3) * 2;
            float e0 = __expf(acc[mi][ni][0] * 0.125f);
            float e1 = __expf(acc[mi][ni][1] * 0.125f);
            float e2 = __expf(acc[mi][ni][2] * 0.125f);
            float e3 = __expf(acc[mi][ni][3] * 0.125f);
            *(float2*)&Cb[(size_t)(row0 + rl) * SS + c]     = make_float2(e0, e1);
            *(float2*)&Cb[(size_t)(row0 + rl + 8) * SS + c] = make_float2(e2, e3);
            p_lo += e0 + e1; p_hi += e2 + e3;
        }
        #pragma unroll
        for (int m = 1; m < 4; m <<= 1) {
            p_lo += __shfl_xor_sync(0xffffffffu, p_lo, m);
            p_hi += __shfl_xor_sync(0xffffffffu, p_hi, m);
        }
        if ((lane & 3) == 0) {
            s_red[rl][warp_n]     = p_lo;
            s_red[rl + 8][warp_n] = p_hi;
        }
    }
    __syncthreads();
    if (tid < 128) {
        float s = s_red[tid][0] + s_red[tid][1] + s_red[tid][2] + s_red[tid][3];
        g_part[((size_t)bh * SS + row0 + tid) * 16 + blockIdx.x] = s;
    }
}

// =====================================================================
// Fold 16 col-block partials per row -> g_rowsum.
// =====================================================================
__global__ __launch_bounds__(256) void rowsum_fold_kernel()
{
    int row = blockIdx.x * 256 + threadIdx.x;
    const float* p = &g_part[(size_t)row * 16];
    float s = 0.0f;
    #pragma unroll
    for (int i = 0; i < 16; i++) s += p[i];
    g_rowsum[row] = s;
}

// =====================================================================
// PV (HMMA) with FUSED normalization:
//  - reads unnormalized attw, scales rows by 1/rowsum while loading
//  - writes the normalized attw back (replaces norm_kernel, bit-exact)
//  - computes g_attn = P_norm @ V via bf16-split HMMA
// CTA 128x64, BK=32, 8 warps (4m x 2n), warp tile 32x32.
// V fragments via ldmatrix.trans from natural [k][n] layout.
// Grid: (16, 1, 32)
// =====================================================================
__global__ __launch_bounds__(256) void mma_pv_kernel(float* __restrict__ attw)
{
    __shared__ __align__(16) uint16_t Ah[128][40];
    __shared__ __align__(16) uint16_t Al[128][40];
    __shared__ __align__(16) uint16_t Bh[32][72];
    __shared__ __align__(16) uint16_t Bl[32][72];
    __shared__ float s_inv[128];

    const int tid = threadIdx.x;
    const int lane = tid & 31, wid = tid >> 5;
    const int warp_m = wid >> 1, warp_n = wid & 1;        // 4 x 2
    const int bh = blockIdx.z;
    const int b = bh >> 4, h = bh & 15;
    const int row0 = blockIdx.x * 128;

    float* Pb = attw + (size_t)bh * SS * SS;
    const float* Vb = g_qkv + (size_t)b * SS * E3 + 2 * EB + h * DH;

    if (tid < 128)
        s_inv[tid] = 1.0f / g_rowsum[(size_t)bh * SS + row0 + tid];
    __syncthreads();

    float acc[2][4][4];
    #pragma unroll
    for (int mi = 0; mi < 2; mi++)
        #pragma unroll
        for (int ni = 0; ni < 4; ni++)
            #pragma unroll
            for (int f = 0; f < 4; f++) acc[mi][ni][f] = 0.0f;

    for (int k0 = 0; k0 < SS; k0 += 32) {
        // A = P rows, scaled by inv; write normalized value back to attw
        #pragma unroll
        for (int i = 0; i < 4; i++) {
            int idx = tid + i * 256;
            int r = idx >> 3, c4 = idx & 7;
            float inv = s_inv[r];
            float* pp = &Pb[(size_t)(row0 + r) * SS + k0 + c4 * 4];
            float4 va = *(const float4*)pp;
            va.x *= inv; va.y *= inv; va.z *= inv; va.w *= inv;
            *(float4*)pp = va;                      // normalized attw out
            uint32_t h0, l0, h1, l1;
            split2(va.x, va.y, h0, l0); split2(va.z, va.w, h1, l1);
            *(uint32_t*)&Ah[r][c4 * 4]     = h0; *(uint32_t*)&Ah[r][c4 * 4 + 2] = h1;
            *(uint32_t*)&Al[r][c4 * 4]     = l0; *(uint32_t*)&Al[r][c4 * 4 + 2] = l1;
        }
        // B = V chunk [32 k][64 n], natural layout (trans at ldmatrix time)
        #pragma unroll
        for (int i = 0; i < 2; i++) {
            int idx = tid + i * 256;                // 0..511
            int vk = idx >> 4, c4 = idx & 15;
            float4 vv = *(const float4*)&Vb[(size_t)(k0 + vk) * E3 + c4 * 4];
            uint32_t h0, l0, h1, l1;
            split2(vv.x, vv.y, h0, l0); split2(vv.z, vv.w, h1, l1);
            *(uint32_t*)&Bh[vk][c4 * 4]     = h0; *(uint32_t*)&Bh[vk][c4 * 4 + 2] = h1;
            *(uint32_t*)&Bl[vk][c4 * 4]     = l0; *(uint32_t*)&Bl[vk][c4 * 4 + 2] = l1;
        }
        __syncthreads();

        #pragma unroll
        for (int ks = 0; ks < 2; ks++) {
            const int ka = ks * 16 + ((lane >> 4) << 3);
            uint32_t ah[2][4], al_[2][4];
            #pragma unroll
            for (int mi = 0; mi < 2; mi++) {
                int r = warp_m * 32 + mi * 16 + (lane & 15);
                LDSM_X4(ah[mi],  smem_u32(&Ah[r][ka]));
                LDSM_X4(al_[mi], smem_u32(&Al[r][ka]));
            }
            // trans B: lane r(0..15) -> &B[k0s + r][n0]
            const int krow = ks * 16 + (lane & 15);
            uint32_t bh[4][2], bl_[4][2];
            #pragma unroll
            for (int ni = 0; ni < 4; ni++) {
                int n0 = warp_n * 32 + ni * 8;
                LDSM_X2_TRANS(bh[ni],  smem_u32(&Bh[krow][n0]));
                LDSM_X2_TRANS(bl_[ni], smem_u32(&Bl[krow][n0]));
            }
            #pragma unroll
            for (int mi = 0; mi < 2; mi++)
                #pragma unroll
                for (int ni = 0; ni < 4; ni++) {
                    MMA_BF16(acc[mi][ni], ah[mi],  bh[ni]);
                    MMA_BF16(acc[mi][ni], ah[mi],  bl_[ni]);
                    MMA_BF16(acc[mi][ni], al_[mi], bh[ni]);
                }
        }
        __syncthreads();
    }

    // epilogue: g_attn[b, s, h*64 + c]
    #pragma unroll
    for (int mi = 0; mi < 2; mi++) {
        int s0 = row0 + warp_m * 32 + mi * 16 + (lane >> 2);
        #pragma unroll
        for (int ni = 0; ni < 4; ni++) {
            int c = warp_n * 32 + ni * 8 + (lane & 3) * 2;
            float* o0 = &g_attn[(size_t)(b * SS + s0) * EB + h * DH + c];
            float* o1 = &g_attn[(size_t)(b * SS + s0 + 8) * EB + h * DH + c];
            *(float2*)o0 = make_float2(acc[mi][ni][0], acc[mi][ni][1]);
            *(float2*)o1 = make_float2(acc[mi][ni][2], acc[mi][ni][3]);
        }
    }
}

// =====================================================================
extern "C" void kernel_launch(void* const* d_in, const int* in_sizes, int n_in,
                              void* d_out, int out_size)
{
    (void)in_sizes; (void)n_in; (void)out_size;
    const float* x     = (const float*)d_in[0];
    const float* qkv_w = (const float*)d_in[1];
    const float* qkv_b = (const float*)d_in[2];
    const float* out_w = (const float*)d_in[3];
    const float* out_b = (const float*)d_in[4];

    float* out  = (float*)d_out;                  // output: [2,2048,1024]
    float* attw = out + (size_t)MT * EB;          // attn_weights: [2,16,2048,2048]

    float* d_qkv  = nullptr;
    float* d_attn = nullptr;
    cudaGetSymbolAddress((void**)&d_qkv,  g_qkv);
    cudaGetSymbolAddress((void**)&d_attn, g_attn);

    // 1. QKV projection (HMMA)
    {
        dim3 grid(E3 / 128, MT / 128);
        mma_gemm_bias_nt<<<grid, 256>>>(x, qkv_w, qkv_b, d_qkv, MT, E3, EB);
    }
    // 2. scores + exp + row partials (HMMA)
    {
        dim3 grid(SS / 128, SS / 128, BB * HN);
        mma_scores_kernel<<<grid, 256>>>(attw);
    }
    // 3. fold partials
    rowsum_fold_kernel<<<BB * HN * SS / 256, 256>>>();
    // 4. P @ V with fused normalization (writes normalized attw + g_attn)
    {
        dim3 grid(SS / 128, 1, BB * HN);
        mma_pv_kernel<<<grid, 256>>>(attw);
    }
    // 5. out projection (HMMA)
    {
        dim3 grid(EB / 128, MT / 128);
        mma_gemm_bias_nt<<<grid, 256>>>(d_attn, out_w, out_b, out, MT, EB, EB);
    }
}

// round 12
// speedup vs baseline: 3.3400x; 1.5044x over previous
#include <cuda_runtime.h>
#include <cuda_bf16.h>
#include <cstdint>

#define EB    1024
#define HN    16
#define DH    64
#define BB    2
#define SS    2048
#define MT    (BB*SS)       // 4096
#define E3    (3*EB)        // 3072

typedef unsigned long long u64;

// Scratch (device globals — allocation is forbidden)
__device__ float g_qkv[(size_t)MT * E3];      // [token][3E]
__device__ float g_attn[(size_t)MT * EB];     // [token][E]
__device__ float g_rowsum[BB * HN * SS];
__device__ float g_part[(size_t)BB * HN * SS * 16];

// ---------------- HMMA (mma.sync) helpers — sm_80-era PTX ----------------
__device__ __forceinline__ uint32_t smem_u32(const void* p) {
    uint32_t a;
    asm("{ .reg .u64 t; cvta.to.shared.u64 t, %1; cvt.u32.u64 %0, t; }" : "=r"(a) : "l"(p));
    return a;
}
#define LDSM_X4(r, addr) \
    asm volatile("ldmatrix.sync.aligned.m8n8.x4.shared.b16 {%0,%1,%2,%3}, [%4];" \
        : "=r"((r)[0]), "=r"((r)[1]), "=r"((r)[2]), "=r"((r)[3]) : "r"(addr))
#define LDSM_X2(r, addr) \
    asm volatile("ldmatrix.sync.aligned.m8n8.x2.shared.b16 {%0,%1}, [%2];" \
        : "=r"((r)[0]), "=r"((r)[1]) : "r"(addr))
#define LDSM_X2_TRANS(r, addr) \
    asm volatile("ldmatrix.sync.aligned.m8n8.x2.trans.shared.b16 {%0,%1}, [%2];" \
        : "=r"((r)[0]), "=r"((r)[1]) : "r"(addr))
#define MMA_BF16(d, a, b) \
    asm volatile("mma.sync.aligned.m16n8k16.row.col.f32.bf16.bf16.f32 " \
        "{%0,%1,%2,%3}, {%4,%5,%6,%7}, {%8,%9}, {%0,%1,%2,%3};" \
        : "+f"((d)[0]), "+f"((d)[1]), "+f"((d)[2]), "+f"((d)[3]) \
        : "r"((a)[0]), "r"((a)[1]), "r"((a)[2]), "r"((a)[3]), \
          "r"((b)[0]), "r"((b)[1]))

// split two fp32 into bf16-hi pair and bf16-lo pair (packed u32: lo half = x0)
__device__ __forceinline__ void split2(float x0, float x1, uint32_t& hi2, uint32_t& lo2) {
    asm("cvt.rn.bf16x2.f32 %0, %1, %2;" : "=r"(hi2) : "f"(x1), "f"(x0));
    float h0 = __uint_as_float(hi2 << 16);
    float h1 = __uint_as_float(hi2 & 0xFFFF0000u);
    float r0 = x0 - h0, r1 = x1 - h1;
    asm("cvt.rn.bf16x2.f32 %0, %1, %2;" : "=r"(lo2) : "f"(r1), "f"(r0));
}

// =====================================================================
// HMMA GEMM: C[M,N] = A[M,K] @ B[N,K]^T + bias[N]
// CTA 128x128, BK=32, 8 warps (2m x 4n), register-prefetch pipelined.
// =====================================================================
__global__ __launch_bounds__(256) void mma_gemm_bias_nt(
    const float* __restrict__ A, const float* __restrict__ B,
    const float* __restrict__ bias, float* __restrict__ C,
    int M, int N, int K)
{
    __shared__ __align__(16) uint16_t Ah[128][40];
    __shared__ __align__(16) uint16_t Al[128][40];
    __shared__ __align__(16) uint16_t Bh[128][40];
    __shared__ __align__(16) uint16_t Bl[128][40];

    const int tid = threadIdx.x;
    const int lane = tid & 31, wid = tid >> 5;
    const int warp_m = wid >> 2, warp_n = wid & 3;
    const int row0 = blockIdx.y * 128, col0 = blockIdx.x * 128;
    const int lr = tid >> 3, lc4 = tid & 7;         // row 0..31 base, float4-col

    float acc[4][4][4];
    #pragma unroll
    for (int mi = 0; mi < 4; mi++)
        #pragma unroll
        for (int ni = 0; ni < 4; ni++)
            #pragma unroll
            for (int f = 0; f < 4; f++) acc[mi][ni][f] = 0.0f;

    float4 pa[4], pb[4];
    #pragma unroll
    for (int i = 0; i < 4; i++) {
        int r = lr + i * 32;
        pa[i] = *(const float4*)&A[(size_t)(row0 + r) * K + lc4 * 4];
        pb[i] = *(const float4*)&B[(size_t)(col0 + r) * K + lc4 * 4];
    }

    for (int k0 = 0; k0 < K; k0 += 32) {
        // store phase: split regs -> smem
        #pragma unroll
        for (int i = 0; i < 4; i++) {
            int r = lr + i * 32;
            uint32_t h0, l0, h1, l1;
            split2(pa[i].x, pa[i].y, h0, l0); split2(pa[i].z, pa[i].w, h1, l1);
            *(uint32_t*)&Ah[r][lc4 * 4]     = h0; *(uint32_t*)&Ah[r][lc4 * 4 + 2] = h1;
            *(uint32_t*)&Al[r][lc4 * 4]     = l0; *(uint32_t*)&Al[r][lc4 * 4 + 2] = l1;
            split2(pb[i].x, pb[i].y, h0, l0); split2(pb[i].z, pb[i].w, h1, l1);
            *(uint32_t*)&Bh[r][lc4 * 4]     = h0; *(uint32_t*)&Bh[r][lc4 * 4 + 2] = h1;
            *(uint32_t*)&Bl[r][lc4 * 4]     = l0; *(uint32_t*)&Bl[r][lc4 * 4 + 2] = l1;
        }
        __syncthreads();

        // prefetch next chunk (latency overlapped with MMA phase)
        if (k0 + 32 < K) {
            #pragma unroll
            for (int i = 0; i < 4; i++) {
                int r = lr + i * 32;
                pa[i] = *(const float4*)&A[(size_t)(row0 + r) * K + k0 + 32 + lc4 * 4];
                pb[i] = *(const float4*)&B[(size_t)(col0 + r) * K + k0 + 32 + lc4 * 4];
            }
        }

        #pragma unroll
        for (int ks = 0; ks < 2; ks++) {
            const int ka = ks * 16 + ((lane >> 4) << 3);
            uint32_t ah[4][4], al_[4][4];
            #pragma unroll
            for (int mi = 0; mi < 4; mi++) {
                int r = warp_m * 64 + mi * 16 + (lane & 15);
                LDSM_X4(ah[mi],  smem_u32(&Ah[r][ka]));
                LDSM_X4(al_[mi], smem_u32(&Al[r][ka]));
            }
            const int kb = ks * 16 + ((lane >> 3) & 1) * 8;
            uint32_t bh[4][2], bl_[4][2];
            #pragma unroll
            for (int ni = 0; ni < 4; ni++) {
                int r = warp_n * 32 + ni * 8 + (lane & 7);
                LDSM_X2(bh[ni],  smem_u32(&Bh[r][kb]));
                LDSM_X2(bl_[ni], smem_u32(&Bl[r][kb]));
            }
            #pragma unroll
            for (int mi = 0; mi < 4; mi++)
                #pragma unroll
                for (int ni = 0; ni < 4; ni++) {
                    MMA_BF16(acc[mi][ni], ah[mi],  bh[ni]);
                    MMA_BF16(acc[mi][ni], ah[mi],  bl_[ni]);
                    MMA_BF16(acc[mi][ni], al_[mi], bh[ni]);
                }
        }
        __syncthreads();
    }

    #pragma unroll
    for (int mi = 0; mi < 4; mi++) {
        int r0 = row0 + warp_m * 64 + mi * 16 + (lane >> 2);
        #pragma unroll
        for (int ni = 0; ni < 4; ni++) {
            int c = col0 + warp_n * 32 + ni * 8 + (lane & 3) * 2;
            float2 bv = *(const float2*)&bias[c];
            *(float2*)&C[(size_t)r0 * N + c] =
                make_float2(acc[mi][ni][0] + bv.x, acc[mi][ni][1] + bv.y);
            *(float2*)&C[(size_t)(r0 + 8) * N + c] =
                make_float2(acc[mi][ni][2] + bv.x, acc[mi][ni][3] + bv.y);
        }
    }
}

// =====================================================================
// Scores (HMMA): attw = exp((Q·K)/8) unnormalized + row partials.
// K=64 (2 chunks), register-prefetch pipelined. Grid: (16, 16, 32)
// =====================================================================
__global__ __launch_bounds__(256) void mma_scores_kernel(float* __restrict__ attw)
{
    __shared__ __align__(16) uint16_t Ah[128][40];
    __shared__ __align__(16) uint16_t Al[128][40];
    __shared__ __align__(16) uint16_t Bh[128][40];
    __shared__ __align__(16) uint16_t Bl[128][40];
    __shared__ float s_red[128][4];

    const int tid = threadIdx.x;
    const int lane = tid & 31, wid = tid >> 5;
    const int warp_m = wid >> 2, warp_n = wid & 3;
    const int bh = blockIdx.z;
    const int b = bh >> 4, h = bh & 15;
    const int row0 = blockIdx.y * 128, col0 = blockIdx.x * 128;
    const int lr = tid >> 3, lc4 = tid & 7;

    const float* Qb = g_qkv + (size_t)b * SS * E3 + h * DH;
    const float* Kb = Qb + EB;

    float acc[4][4][4];
    #pragma unroll
    for (int mi = 0; mi < 4; mi++)
        #pragma unroll
        for (int ni = 0; ni < 4; ni++)
            #pragma unroll
            for (int f = 0; f < 4; f++) acc[mi][ni][f] = 0.0f;

    float4 pa[4], pb[4];
    #pragma unroll
    for (int i = 0; i < 4; i++) {
        int r = lr + i * 32;
        pa[i] = *(const float4*)&Qb[(size_t)(row0 + r) * E3 + lc4 * 4];
        pb[i] = *(const float4*)&Kb[(size_t)(col0 + r) * E3 + lc4 * 4];
    }

    #pragma unroll
    for (int k0 = 0; k0 < DH; k0 += 32) {
        #pragma unroll
        for (int i = 0; i < 4; i++) {
            int r = lr + i * 32;
            uint32_t h0, l0, h1, l1;
            split2(pa[i].x, pa[i].y, h0, l0); split2(pa[i].z, pa[i].w, h1, l1);
            *(uint32_t*)&Ah[r][lc4 * 4]     = h0; *(uint32_t*)&Ah[r][lc4 * 4 + 2] = h1;
            *(uint32_t*)&Al[r][lc4 * 4]     = l0; *(uint32_t*)&Al[r][lc4 * 4 + 2] = l1;
            split2(pb[i].x, pb[i].y, h0, l0); split2(pb[i].z, pb[i].w, h1, l1);
            *(uint32_t*)&Bh[r][lc4 * 4]     = h0; *(uint32_t*)&Bh[r][lc4 * 4 + 2] = h1;
            *(uint32_t*)&Bl[r][lc4 * 4]     = l0; *(uint32_t*)&Bl[r][lc4 * 4 + 2] = l1;
        }
        __syncthreads();

        if (k0 + 32 < DH) {
            #pragma unroll
            for (int i = 0; i < 4; i++) {
                int r = lr + i * 32;
                pa[i] = *(const float4*)&Qb[(size_t)(row0 + r) * E3 + k0 + 32 + lc4 * 4];
                pb[i] = *(const float4*)&Kb[(size_t)(col0 + r) * E3 + k0 + 32 + lc4 * 4];
            }
        }

        #pragma unroll
        for (int ks = 0; ks < 2; ks++) {
            const int ka = ks * 16 + ((lane >> 4) << 3);
            uint32_t ah[4][4], al_[4][4];
            #pragma unroll
            for (int mi = 0; mi < 4; mi++) {
                int r = warp_m * 64 + mi * 16 + (lane & 15);
                LDSM_X4(ah[mi],  smem_u32(&Ah[r][ka]));
                LDSM_X4(al_[mi], smem_u32(&Al[r][ka]));
            }
            const int kb = ks * 16 + ((lane >> 3) & 1) * 8;
            uint32_t bh[4][2], bl_[4][2];
            #pragma unroll
            for (int ni = 0; ni < 4; ni++) {
                int r = warp_n * 32 + ni * 8 + (lane & 7);
                LDSM_X2(bh[ni],  smem_u32(&Bh[r][kb]));
                LDSM_X2(bl_[ni], smem_u32(&Bl[r][kb]));
            }
            #pragma unroll
            for (int mi = 0; mi < 4; mi++)
                #pragma unroll
                for (int ni = 0; ni < 4; ni++) {
                    MMA_BF16(acc[mi][ni], ah[mi],  bh[ni]);
                    MMA_BF16(acc[mi][ni], ah[mi],  bl_[ni]);
                    MMA_BF16(acc[mi][ni], al_[mi], bh[ni]);
                }
        }
        __syncthreads();
    }

    float* Cb = attw + (size_t)bh * SS * SS;
    #pragma unroll
    for (int mi = 0; mi < 4; mi++) {
        int rl = warp_m * 64 + mi * 16 + (lane >> 2);
        float p_lo = 0.0f, p_hi = 0.0f;
        #pragma unroll
        for (int ni = 0; ni < 4; ni++) {
            int c = col0 + warp_n * 32 + ni * 8 + (lane & 3) * 2;
            float e0 = __expf(acc[mi][ni][0] * 0.125f);
            float e1 = __expf(acc[mi][ni][1] * 0.125f);
            float e2 = __expf(acc[mi][ni][2] * 0.125f);
            float e3 = __expf(acc[mi][ni][3] * 0.125f);
            *(float2*)&Cb[(size_t)(row0 + rl) * SS + c]     = make_float2(e0, e1);
            *(float2*)&Cb[(size_t)(row0 + rl + 8) * SS + c] = make_float2(e2, e3);
            p_lo += e0 + e1; p_hi += e2 + e3;
        }
        #pragma unroll
        for (int m = 1; m < 4; m <<= 1) {
            p_lo += __shfl_xor_sync(0xffffffffu, p_lo, m);
            p_hi += __shfl_xor_sync(0xffffffffu, p_hi, m);
        }
        if ((lane & 3) == 0) {
            s_red[rl][warp_n]     = p_lo;
            s_red[rl + 8][warp_n] = p_hi;
        }
    }
    __syncthreads();
    if (tid < 128) {
        float s = s_red[tid][0] + s_red[tid][1] + s_red[tid][2] + s_red[tid][3];
        g_part[((size_t)bh * SS + row0 + tid) * 16 + blockIdx.x] = s;
    }
}

// =====================================================================
// Fold 16 col-block partials per row -> g_rowsum.
// =====================================================================
__global__ __launch_bounds__(256) void rowsum_fold_kernel()
{
    int row = blockIdx.x * 256 + threadIdx.x;
    const float* p = &g_part[(size_t)row * 16];
    float s = 0.0f;
    #pragma unroll
    for (int i = 0; i < 16; i++) s += p[i];
    g_rowsum[row] = s;
}

// =====================================================================
// PV (HMMA) with fused normalization, register-prefetch pipelined.
// CTA 128x64, BK=32, 8 warps (4m x 2n). Grid: (16, 1, 32)
// =====================================================================
__global__ __launch_bounds__(256) void mma_pv_kernel(float* __restrict__ attw)
{
    __shared__ __align__(16) uint16_t Ah[128][40];
    __shared__ __align__(16) uint16_t Al[128][40];
    __shared__ __align__(16) uint16_t Bh[32][72];
    __shared__ __align__(16) uint16_t Bl[32][72];
    __shared__ float s_inv[128];

    const int tid = threadIdx.x;
    const int lane = tid & 31, wid = tid >> 5;
    const int warp_m = wid >> 1, warp_n = wid & 1;
    const int bh = blockIdx.z;
    const int b = bh >> 4, h = bh & 15;
    const int row0 = blockIdx.x * 128;
    const int lr = tid >> 3, lc4 = tid & 7;          // A tile mapping
    const int vk = tid >> 4, vc4 = tid & 15;         // V tile mapping

    float* Pb = attw + (size_t)bh * SS * SS;
    const float* Vb = g_qkv + (size_t)b * SS * E3 + 2 * EB + h * DH;

    if (tid < 128)
        s_inv[tid] = 1.0f / g_rowsum[(size_t)bh * SS + row0 + tid];
    __syncthreads();

    float acc[2][4][4];
    #pragma unroll
    for (int mi = 0; mi < 2; mi++)
        #pragma unroll
        for (int ni = 0; ni < 4; ni++)
            #pragma unroll
            for (int f = 0; f < 4; f++) acc[mi][ni][f] = 0.0f;

    float4 pa[4], pv[2];
    #pragma unroll
    for (int i = 0; i < 4; i++)
        pa[i] = *(const float4*)&Pb[(size_t)(row0 + lr + i * 32) * SS + lc4 * 4];
    #pragma unroll
    for (int i = 0; i < 2; i++)
        pv[i] = *(const float4*)&Vb[(size_t)(vk + i * 16) * E3 + vc4 * 4];

    for (int k0 = 0; k0 < SS; k0 += 32) {
        // store phase: normalize A regs, write back, split to smem; split V
        #pragma unroll
        for (int i = 0; i < 4; i++) {
            int r = lr + i * 32;
            float inv = s_inv[r];
            float4 va = pa[i];
            va.x *= inv; va.y *= inv; va.z *= inv; va.w *= inv;
            *(float4*)&Pb[(size_t)(row0 + r) * SS + k0 + lc4 * 4] = va;  // normalized attw
            uint32_t h0, l0, h1, l1;
            split2(va.x, va.y, h0, l0); split2(va.z, va.w, h1, l1);
            *(uint32_t*)&Ah[r][lc4 * 4]     = h0; *(uint32_t*)&Ah[r][lc4 * 4 + 2] = h1;
            *(uint32_t*)&Al[r][lc4 * 4]     = l0; *(uint32_t*)&Al[r][lc4 * 4 + 2] = l1;
        }
        #pragma unroll
        for (int i = 0; i < 2; i++) {
            int k = vk + i * 16;
            uint32_t h0, l0, h1, l1;
            split2(pv[i].x, pv[i].y, h0, l0); split2(pv[i].z, pv[i].w, h1, l1);
            *(uint32_t*)&Bh[k][vc4 * 4]     = h0; *(uint32_t*)&Bh[k][vc4 * 4 + 2] = h1;
            *(uint32_t*)&Bl[k][vc4 * 4]     = l0; *(uint32_t*)&Bl[k][vc4 * 4 + 2] = l1;
        }
        __syncthreads();

        // prefetch next chunk
        if (k0 + 32 < SS) {
            #pragma unroll
            for (int i = 0; i < 4; i++)
                pa[i] = *(const float4*)&Pb[(size_t)(row0 + lr + i * 32) * SS + k0 + 32 + lc4 * 4];
            #pragma unroll
            for (int i = 0; i < 2; i++)
                pv[i] = *(const float4*)&Vb[(size_t)(k0 + 32 + vk + i * 16) * E3 + vc4 * 4];
        }

        #pragma unroll
        for (int ks = 0; ks < 2; ks++) {
            const int ka = ks * 16 + ((lane >> 4) << 3);
            uint32_t ah[2][4], al_[2][4];
            #pragma unroll
            for (int mi = 0; mi < 2; mi++) {
                int r = warp_m * 32 + mi * 16 + (lane & 15);
                LDSM_X4(ah[mi],  smem_u32(&Ah[r][ka]));
                LDSM_X4(al_[mi], smem_u32(&Al[r][ka]));
            }
            const int krow = ks * 16 + (lane & 15);
            uint32_t bh[4][2], bl_[4][2];
            #pragma unroll
            for (int ni = 0; ni < 4; ni++) {
                int n0 = warp_n * 32 + ni * 8;
                LDSM_X2_TRANS(bh[ni],  smem_u32(&Bh[krow][n0]));
                LDSM_X2_TRANS(bl_[ni], smem_u32(&Bl[krow][n0]));
            }
            #pragma unroll
            for (int mi = 0; mi < 2; mi++)
                #pragma unroll
                for (int ni = 0; ni < 4; ni++) {
                    MMA_BF16(acc[mi][ni], ah[mi],  bh[ni]);
                    MMA_BF16(acc[mi][ni], ah[mi],  bl_[ni]);
                    MMA_BF16(acc[mi][ni], al_[mi], bh[ni]);
                }
        }
        __syncthreads();
    }

    #pragma unroll
    for (int mi = 0; mi < 2; mi++) {
        int s0 = row0 + warp_m * 32 + mi * 16 + (lane >> 2);
        #pragma unroll
        for (int ni = 0; ni < 4; ni++) {
            int c = warp_n * 32 + ni * 8 + (lane & 3) * 2;
            float* o0 = &g_attn[(size_t)(b * SS + s0) * EB + h * DH + c];
            float* o1 = &g_attn[(size_t)(b * SS + s0 + 8) * EB + h * DH + c];
            *(float2*)o0 = make_float2(acc[mi][ni][0], acc[mi][ni][1]);
            *(float2*)o1 = make_float2(acc[mi][ni][2], acc[mi][ni][3]);
        }
    }
}

// =====================================================================
extern "C" void kernel_launch(void* const* d_in, const int* in_sizes, int n_in,
                              void* d_out, int out_size)
{
    (void)in_sizes; (void)n_in; (void)out_size;
    const float* x     = (const float*)d_in[0];
    const float* qkv_w = (const float*)d_in[1];
    const float* qkv_b = (const float*)d_in[2];
    const float* out_w = (const float*)d_in[3];
    const float* out_b = (const float*)d_in[4];

    float* out  = (float*)d_out;                  // output: [2,2048,1024]
    float* attw = out + (size_t)MT * EB;          // attn_weights: [2,16,2048,2048]

    float* d_qkv  = nullptr;
    float* d_attn = nullptr;
    cudaGetSymbolAddress((void**)&d_qkv,  g_qkv);
    cudaGetSymbolAddress((void**)&d_attn, g_attn);

    // 1. QKV projection (HMMA, pipelined)
    {
        dim3 grid(E3 / 128, MT / 128);
        mma_gemm_bias_nt<<<grid, 256>>>(x, qkv_w, qkv_b, d_qkv, MT, E3, EB);
    }
    // 2. scores + exp + row partials (HMMA, pipelined)
    {
        dim3 grid(SS / 128, SS / 128, BB * HN);
        mma_scores_kernel<<<grid, 256>>>(attw);
    }
    // 3. fold partials
    rowsum_fold_kernel<<<BB * HN * SS / 256, 256>>>();
    // 4. P @ V with fused normalization (HMMA, pipelined)
    {
        dim3 grid(SS / 128, 1, BB * HN);
        mma_pv_kernel<<<grid, 256>>>(attw);
    }
    // 5. out projection (HMMA, pipelined)
    {
        dim3 grid(EB / 128, MT / 128);
        mma_gemm_bias_nt<<<grid, 256>>>(d_attn, out_w, out_b, out, MT, EB, EB);
    }
}